// round 1
// baseline (speedup 1.0000x reference)
#include <cuda_runtime.h>
#include <math.h>
#include <stdint.h>

// Problem constants (fixed by setup_inputs)
#define B_   64
#define S_   8
#define DK_  64
#define DA_  2048
#define N_   100000
#define KTOT 512        // S_*DK_
#define KMAX 32
#define TN   64         // n-tile for score GEMM
#define EPSF 1e-8f

// ---------------- device scratch (no allocations allowed) ----------------
__device__ float g_qpart[16 * B_ * KTOT];   // split-K partials (deterministic)
__device__ float g_q[B_ * KTOT];            // raw queries [b][s*64+k]
__device__ float g_qhat[B_ * KTOT];         // w_s * qn    [b][s*64+k]
__device__ float g_s[(size_t)B_ * N_];      // scores      [b][n]  (25.6 MB)

// ---------------- K1a: queries partial GEMM (split over a) ----------------
// grid (16 a-splits, 8 sk-tiles), 256 threads. C[64b x 64sk] over 128 a.
__global__ void __launch_bounds__(256) k_proj_partial(const float* __restrict__ z,
                                                      const float* __restrict__ wq) {
    __shared__ float zt[64][33];
    __shared__ float wt[64][33];
    int tid = threadIdx.x;
    int tx = tid & 15, ty = tid >> 4;
    int a_base = blockIdx.x * 128;
    int sk_base = blockIdx.y * 64;
    float acc[4][4] = {};
    for (int t = 0; t < 4; t++) {
        int a0 = a_base + t * 32;
        for (int idx = tid; idx < 64 * 32; idx += 256) {
            int r = idx >> 5, c = idx & 31;
            zt[r][c] = z[r * DA_ + a0 + c];
            wt[r][c] = wq[(size_t)(sk_base + r) * DA_ + a0 + c];
        }
        __syncthreads();
#pragma unroll
        for (int a = 0; a < 32; a++) {
            float zv[4], wv[4];
#pragma unroll
            for (int i = 0; i < 4; i++) zv[i] = zt[4 * ty + i][a];
#pragma unroll
            for (int j = 0; j < 4; j++) wv[j] = wt[4 * tx + j][a];
#pragma unroll
            for (int i = 0; i < 4; i++)
#pragma unroll
                for (int j = 0; j < 4; j++) acc[i][j] += zv[i] * wv[j];
        }
        __syncthreads();
    }
#pragma unroll
    for (int i = 0; i < 4; i++)
#pragma unroll
        for (int j = 0; j < 4; j++)
            g_qpart[blockIdx.x * (B_ * KTOT) + (4 * ty + i) * KTOT + sk_base + 4 * tx + j] = acc[i][j];
}

// ---------------- K1r: deterministic split-K reduction ----------------
__global__ void k_proj_reduce() {
    int idx = blockIdx.x * blockDim.x + threadIdx.x;
    if (idx < B_ * KTOT) {
        float s = 0.f;
#pragma unroll
        for (int p = 0; p < 16; p++) s += g_qpart[p * (B_ * KTOT) + idx];
        g_q[idx] = s;
    }
}

// ---------------- K1b: normalize queries, fold softmax(aspect_weights) ----
// 512 warps: warp -> (b, s). Each lane handles 2 of the 64 k-elements.
__global__ void k_qnorm(const float* __restrict__ aw) {
    int gw = (blockIdx.x * blockDim.x + threadIdx.x) >> 5;
    int lane = threadIdx.x & 31;
    if (gw >= B_ * S_) return;
    int b = gw >> 3, s = gw & 7;
    int base = b * KTOT + s * 64;
    float q0 = g_q[base + lane];
    float q1 = g_q[base + 32 + lane];
    float ss = q0 * q0 + q1 * q1;
#pragma unroll
    for (int off = 16; off > 0; off >>= 1) ss += __shfl_xor_sync(0xFFFFFFFFu, ss, off);
    // softmax over the 8 aspect weights (tiny, redundant per thread)
    float m = aw[0];
#pragma unroll
    for (int i = 1; i < 8; i++) m = fmaxf(m, aw[i]);
    float den = 0.f, es = 0.f;
#pragma unroll
    for (int i = 0; i < 8; i++) {
        float e = expf(aw[i] - m);
        den += e;
        if (i == s) es = e;
    }
    float wsm = es / den;
    float scale = wsm / (sqrtf(ss) + EPSF);
    g_qhat[base + lane] = q0 * scale;
    g_qhat[base + 32 + lane] = q1 * scale;
}

// ---------------- K2: main score GEMM with fused key normalization --------
// grid: ceil(N/TN) blocks x 256 threads. smem: kt[512][64] normalized keys.
// out: g_s[b][n] = qhat[b,:] . kn[:,n]
__global__ void __launch_bounds__(256) k_scores(const float* __restrict__ keys) {
    extern __shared__ float kt[];
    int tid = threadIdx.x;
    int n0 = blockIdx.x * TN;

    // load + normalize keys: each thread owns 2 (s,n) rows of 64 floats
    for (int rr = tid; rr < 512; rr += 256) {
        int s = rr >> 6, nl = rr & 63;
        int n = n0 + nl;
        if (n < N_) {
            const float4* src = reinterpret_cast<const float4*>(keys + ((size_t)s * N_ + n) * DK_);
            float4 v[16];
            float ss = 0.f;
#pragma unroll
            for (int j = 0; j < 16; j++) {
                float4 t = __ldg(src + j);
                v[j] = t;
                ss += t.x * t.x + t.y * t.y + t.z * t.z + t.w * t.w;
            }
            float inv = 1.f / (sqrtf(ss) + EPSF);
#pragma unroll
            for (int j = 0; j < 16; j++) {
                int kb = s * 64 + j * 4;
                kt[(kb + 0) * TN + nl] = v[j].x * inv;
                kt[(kb + 1) * TN + nl] = v[j].y * inv;
                kt[(kb + 2) * TN + nl] = v[j].z * inv;
                kt[(kb + 3) * TN + nl] = v[j].w * inv;
            }
        } else {
#pragma unroll
            for (int j = 0; j < 64; j++) kt[(s * 64 + j) * TN + nl] = 0.f;
        }
    }
    __syncthreads();

    int tx = tid & 15, ty = tid >> 4;
    int nb = 4 * tx, b0 = 4 * ty;
    float acc[4][4] = {};
#pragma unroll 2
    for (int kk = 0; kk < KTOT; kk += 4) {
        float4 k0 = *reinterpret_cast<const float4*>(&kt[(kk + 0) * TN + nb]);
        float4 k1 = *reinterpret_cast<const float4*>(&kt[(kk + 1) * TN + nb]);
        float4 k2 = *reinterpret_cast<const float4*>(&kt[(kk + 2) * TN + nb]);
        float4 k3 = *reinterpret_cast<const float4*>(&kt[(kk + 3) * TN + nb]);
        float kv[4][4] = {{k0.x, k0.y, k0.z, k0.w},
                          {k1.x, k1.y, k1.z, k1.w},
                          {k2.x, k2.y, k2.z, k2.w},
                          {k3.x, k3.y, k3.z, k3.w}};
#pragma unroll
        for (int i = 0; i < 4; i++) {
            float4 qv = __ldg(reinterpret_cast<const float4*>(g_qhat + (b0 + i) * KTOT + kk));
            float qq[4] = {qv.x, qv.y, qv.z, qv.w};
#pragma unroll
            for (int l = 0; l < 4; l++)
#pragma unroll
                for (int j = 0; j < 4; j++) acc[i][j] += qq[l] * kv[l][j];
        }
    }
#pragma unroll
    for (int i = 0; i < 4; i++) {
        int n = n0 + nb;
        size_t base = (size_t)(b0 + i) * N_ + n;
        if (n + 3 < N_) {
            *reinterpret_cast<float4*>(&g_s[base]) = make_float4(acc[i][0], acc[i][1], acc[i][2], acc[i][3]);
        } else {
#pragma unroll
            for (int j = 0; j < 4; j++)
                if (n + j < N_) g_s[base + j] = acc[i][j];
        }
    }
}

// ---------------- K3: exact top-32 + alpha per batch row ------------------
__device__ __forceinline__ unsigned flipf(float f) {
    unsigned u = __float_as_uint(f);
    return (u & 0x80000000u) ? ~u : (u | 0x80000000u);
}
__device__ __forceinline__ float unflipf(unsigned u) {
    return __uint_as_float((u & 0x80000000u) ? (u & 0x7FFFFFFFu) : ~u);
}

__global__ void __launch_bounds__(256) k_topk(const float* __restrict__ tau_p,
                                              const float* __restrict__ lam_p,
                                              const int* __restrict__ warm_p,
                                              int has_warm,
                                              float* __restrict__ out,
                                              int out_size) {
    __shared__ unsigned long long sh_cand[256];
    __shared__ float sh_rs[8];
    int b = blockIdx.x;
    int tid = threadIdx.x;
    int lane = tid & 31, wid = tid >> 5;
    float lambda = __ldg(lam_p);
    float tau = __ldg(tau_p);

    // warp-distributed sorted top-32 list (lane j holds j-th smallest key)
    unsigned long long list = 0ull;
    float rs = 0.f;
    const float* srow = g_s + (size_t)b * N_;
    const int ITERS = (N_ + 255) / 256;  // 391
    for (int it = 0; it < ITERS; it++) {
        int n = tid + it * 256;
        unsigned long long key = 0ull;
        if (n < N_) {
            float sv = srow[n];
            float x = lambda * (sv - tau);
            float gg = 1.f / (1.f + __expf(-x));
            rs += gg * __expf(sv);
            key = ((unsigned long long)flipf(sv) << 32) |
                  (unsigned long long)(0xFFFFFFFFu - (unsigned)n);
        }
        unsigned long long cm = __shfl_sync(0xFFFFFFFFu, list, 0);
        unsigned m = __ballot_sync(0xFFFFFFFFu, key > cm);
        while (m) {
            int src = __ffs(m) - 1;
            unsigned long long kk = __shfl_sync(0xFFFFFFFFu, key, src);
            cm = __shfl_sync(0xFFFFFFFFu, list, 0);
            if (kk > cm) {  // uniform condition
                unsigned lt = __ballot_sync(0xFFFFFFFFu, list < kk);
                int pos = __popc(lt);
                unsigned long long dn = __shfl_down_sync(0xFFFFFFFFu, list, 1);
                if (lane < pos - 1) list = dn;
                else if (lane == pos - 1) list = kk;
            }
            m &= m - 1;
        }
    }
    sh_cand[tid] = list;
#pragma unroll
    for (int off = 16; off > 0; off >>= 1) rs += __shfl_xor_sync(0xFFFFFFFFu, rs, off);
    if (lane == 0) sh_rs[wid] = rs;
    __syncthreads();

    if (wid == 0) {
        unsigned long long c[8];
#pragma unroll
        for (int i = 0; i < 8; i++) c[i] = sh_cand[i * 32 + lane];
        float Stot = 0.f;
#pragma unroll
        for (int i = 0; i < 8; i++) Stot += sh_rs[i];

        float myS = 0.f;
        int myN = 0;
        for (int round = 0; round < 32; round++) {
            unsigned long long lm = c[0];
#pragma unroll
            for (int i = 1; i < 8; i++) lm = (c[i] > lm) ? c[i] : lm;
            unsigned long long mm = lm;
#pragma unroll
            for (int off = 16; off > 0; off >>= 1) {
                unsigned long long o = __shfl_xor_sync(0xFFFFFFFFu, mm, off);
                if (o > mm) mm = o;
            }
            unsigned has = __ballot_sync(0xFFFFFFFFu, lm == mm);
            int src = __ffs(has) - 1;
            if (lane == src) {
#pragma unroll
                for (int i = 0; i < 8; i++)
                    if (c[i] == mm) c[i] = 0ull;
            }
            if (lane == round) {
                unsigned hi = (unsigned)(mm >> 32);
                unsigned lo = (unsigned)(mm & 0xFFFFFFFFu);
                myS = unflipf(hi);
                myN = (int)(0xFFFFFFFFu - lo);
            }
        }

        int warm = has_warm ? __ldg(warm_p) : 0;
        float alpha;
        if (warm) {
            float smax = __shfl_sync(0xFFFFFFFFu, myS, 0);
            float e = expf(myS - smax);
            float den = e;
#pragma unroll
            for (int off = 16; off > 0; off >>= 1) den += __shfl_xor_sync(0xFFFFFFFFu, den, off);
            alpha = e / den;
        } else {
            float x = lambda * (myS - tau);
            float gg = 1.f / (1.f + expf(-x));
            float r = gg * expf(myS);
            float nr = r / (Stot + EPSF);
            float snr = nr;
#pragma unroll
            for (int off = 16; off > 0; off >>= 1) snr += __shfl_xor_sync(0xFFFFFFFFu, snr, off);
            alpha = nr / (snr + EPSF);
        }
        out[b * KMAX + lane] = alpha;
        if (out_size >= 2 * B_ * KMAX)
            out[B_ * KMAX + b * KMAX + lane] = (float)myN;
    }
}

// ---------------- host launch ----------------
extern "C" void kernel_launch(void* const* d_in, const int* in_sizes, int n_in,
                              void* d_out, int out_size) {
    const float* z    = (const float*)d_in[0];   // [64,2048]
    const float* keys = (const float*)d_in[1];   // [8,100000,64]
    const float* wq   = (const float*)d_in[2];   // [8,64,2048]
    const float* aw   = (const float*)d_in[3];   // [8]
    const float* tau  = (const float*)d_in[4];   // scalar
    const float* lam  = (const float*)d_in[5];   // scalar
    const int* warm   = (n_in > 6) ? (const int*)d_in[6] : nullptr;

    k_proj_partial<<<dim3(16, 8), 256>>>(z, wq);
    k_proj_reduce<<<128, 256>>>();
    k_qnorm<<<64, 256>>>(aw);

    static int smem_set = 0;
    (void)smem_set;
    cudaFuncSetAttribute(k_scores, cudaFuncAttributeMaxDynamicSharedMemorySize, KTOT * TN * 4);
    k_scores<<<(N_ + TN - 1) / TN, 256, KTOT * TN * 4>>>(keys);

    k_topk<<<B_, 256>>>(tau, lam, warm, warm != nullptr, (float*)d_out, out_size);
}

// round 2
// speedup vs baseline: 1.4433x; 1.4433x over previous
#include <cuda_runtime.h>
#include <math.h>
#include <stdint.h>

// Problem constants (fixed by setup_inputs)
#define B_   64
#define S_   8
#define DK_  64
#define DA_  2048
#define N_   100000
#define KTOT 512        // S_*DK_
#define KMAX 32
#define TNB  256        // n-tile per block in score GEMM
#define NCHK 16         // top-k stage-1 chunks
#define CHSZ (N_ / NCHK) // 6250
#define EPSF 1e-8f

// ---------------- device scratch (no allocations allowed) ----------------
__device__ float g_qpart[16 * B_ * KTOT];   // split-K partials (deterministic)
__device__ float g_q[B_ * KTOT];            // raw queries [b][s*64+k]
__device__ float g_qhat[B_ * KTOT];         // w_s * qn    [b][s*64+k]
__device__ float g_s[(size_t)B_ * N_];      // scores      [b][n]  (25.6 MB)
__device__ float g_rsp[B_ * 512];           // per-(b,block) raw-sum partials
__device__ unsigned long long g_cand[B_ * NCHK * KMAX]; // stage-1 candidates

// ---------------- K1a: queries partial GEMM (split over a) ----------------
__global__ void __launch_bounds__(256) k_proj_partial(const float* __restrict__ z,
                                                      const float* __restrict__ wq) {
    __shared__ float zt[64][33];
    __shared__ float wt[64][33];
    int tid = threadIdx.x;
    int tx = tid & 15, ty = tid >> 4;
    int a_base = blockIdx.x * 128;
    int sk_base = blockIdx.y * 64;
    float acc[4][4] = {};
    for (int t = 0; t < 4; t++) {
        int a0 = a_base + t * 32;
        for (int idx = tid; idx < 64 * 32; idx += 256) {
            int r = idx >> 5, c = idx & 31;
            zt[r][c] = z[r * DA_ + a0 + c];
            wt[r][c] = wq[(size_t)(sk_base + r) * DA_ + a0 + c];
        }
        __syncthreads();
#pragma unroll
        for (int a = 0; a < 32; a++) {
            float zv[4], wv[4];
#pragma unroll
            for (int i = 0; i < 4; i++) zv[i] = zt[4 * ty + i][a];
#pragma unroll
            for (int j = 0; j < 4; j++) wv[j] = wt[4 * tx + j][a];
#pragma unroll
            for (int i = 0; i < 4; i++)
#pragma unroll
                for (int j = 0; j < 4; j++) acc[i][j] += zv[i] * wv[j];
        }
        __syncthreads();
    }
#pragma unroll
    for (int i = 0; i < 4; i++)
#pragma unroll
        for (int j = 0; j < 4; j++)
            g_qpart[blockIdx.x * (B_ * KTOT) + (4 * ty + i) * KTOT + sk_base + 4 * tx + j] = acc[i][j];
}

// ---------------- K1r: deterministic split-K reduction ----------------
__global__ void k_proj_reduce() {
    int idx = blockIdx.x * blockDim.x + threadIdx.x;
    if (idx < B_ * KTOT) {
        float s = 0.f;
#pragma unroll
        for (int p = 0; p < 16; p++) s += g_qpart[p * (B_ * KTOT) + idx];
        g_q[idx] = s;
    }
}

// ---------------- K1b: normalize queries, fold softmax(aspect_weights) ----
__global__ void k_qnorm(const float* __restrict__ aw) {
    int gw = (blockIdx.x * blockDim.x + threadIdx.x) >> 5;
    int lane = threadIdx.x & 31;
    if (gw >= B_ * S_) return;
    int b = gw >> 3, s = gw & 7;
    int base = b * KTOT + s * 64;
    float q0 = g_q[base + lane];
    float q1 = g_q[base + 32 + lane];
    float ss = q0 * q0 + q1 * q1;
#pragma unroll
    for (int off = 16; off > 0; off >>= 1) ss += __shfl_xor_sync(0xFFFFFFFFu, ss, off);
    float m = aw[0];
#pragma unroll
    for (int i = 1; i < 8; i++) m = fmaxf(m, aw[i]);
    float den = 0.f, es = 0.f;
#pragma unroll
    for (int i = 0; i < 8; i++) {
        float e = expf(aw[i] - m);
        den += e;
        if (i == s) es = e;
    }
    float wsm = es / den;
    float scale = wsm / (sqrtf(ss) + EPSF);
    g_qhat[base + lane] = q0 * scale;
    g_qhat[base + 32 + lane] = q1 * scale;
}

// ---------------- K2: score GEMM, f32x2 FMAs, fused key norm + raw-sum ----
// block: 64 b x 256 n. 256 threads: warp w owns b-rows [8w, 8w+8), lanes span n.
// thread tile: 8 b x 8 n (4 f32x2 pairs). Chunked k (64 = one aspect).
// smem: kt[64][256] normalized keys (64KB) + qs[64 b][64 k] (16KB) = 80KB.
__global__ void __launch_bounds__(256, 2) k_scores2(const float* __restrict__ keys,
                                                    const float* __restrict__ tau_p,
                                                    const float* __restrict__ lam_p) {
    extern __shared__ float sm[];
    float* kt = sm;               // [64][TNB]
    float* qs = sm + 64 * TNB;    // [64 b][64 k]
    int tid = threadIdx.x;
    int tx = tid & 31;            // n group: n = n0 + tx*8 .. +7
    int ty = tid >> 5;            // warp: b rows ty*8 .. ty*8+7
    int n0 = blockIdx.x * TNB;
    int nme = n0 + tid;           // the n this thread loads
    bool ld_valid = (nme < N_);

    unsigned long long acc[8][4];
#pragma unroll
    for (int i = 0; i < 8; i++)
#pragma unroll
        for (int j = 0; j < 4; j++) acc[i][j] = 0ull;

    for (int s = 0; s < S_; s++) {
        // -- load & normalize keys for aspect s: thread owns one n-row --
        if (ld_valid) {
            const float4* src = reinterpret_cast<const float4*>(keys + ((size_t)s * N_ + nme) * DK_);
            float ss = 0.f;
#pragma unroll
            for (int j = 0; j < 16; j++) {
                float4 t = __ldg(src + j);
                ss += t.x * t.x + t.y * t.y + t.z * t.z + t.w * t.w;
            }
            float inv = 1.f / (sqrtf(ss) + EPSF);
#pragma unroll
            for (int j = 0; j < 16; j++) {
                float4 t = __ldg(src + j);
                kt[(j * 4 + 0) * TNB + tid] = t.x * inv;
                kt[(j * 4 + 1) * TNB + tid] = t.y * inv;
                kt[(j * 4 + 2) * TNB + tid] = t.z * inv;
                kt[(j * 4 + 3) * TNB + tid] = t.w * inv;
            }
        } else {
#pragma unroll
            for (int j = 0; j < 64; j++) kt[j * TNB + tid] = 0.f;
        }
        // -- stage q chunk: qs[b][k] = g_qhat[b*512 + s*64 + k] --
        for (int idx = tid; idx < 64 * 64; idx += 256) {
            int b = idx >> 6, k = idx & 63;
            qs[b * 64 + k] = g_qhat[b * KTOT + s * 64 + k];
        }
        __syncthreads();

        // -- compute --
#pragma unroll 1
        for (int k4 = 0; k4 < 64; k4 += 4) {
            float4 qv[8];
#pragma unroll
            for (int i = 0; i < 8; i++)
                qv[i] = *reinterpret_cast<const float4*>(&qs[(ty * 8 + i) * 64 + k4]);
#pragma unroll
            for (int kk = 0; kk < 4; kk++) {
                const ulonglong2 kva = *reinterpret_cast<const ulonglong2*>(&kt[(k4 + kk) * TNB + tx * 8]);
                const ulonglong2 kvb = *reinterpret_cast<const ulonglong2*>(&kt[(k4 + kk) * TNB + tx * 8 + 4]);
                unsigned long long kn0 = kva.x, kn1 = kva.y, kn2 = kvb.x, kn3 = kvb.y;
#pragma unroll
                for (int i = 0; i < 8; i++) {
                    float qf = (kk == 0) ? qv[i].x : (kk == 1) ? qv[i].y : (kk == 2) ? qv[i].z : qv[i].w;
                    unsigned qu = __float_as_uint(qf);
                    unsigned long long qd;
                    asm("mov.b64 %0, {%1, %1};" : "=l"(qd) : "r"(qu));
                    asm("fma.rn.f32x2 %0, %1, %2, %0;" : "+l"(acc[i][0]) : "l"(qd), "l"(kn0));
                    asm("fma.rn.f32x2 %0, %1, %2, %0;" : "+l"(acc[i][1]) : "l"(qd), "l"(kn1));
                    asm("fma.rn.f32x2 %0, %1, %2, %0;" : "+l"(acc[i][2]) : "l"(qd), "l"(kn2));
                    asm("fma.rn.f32x2 %0, %1, %2, %0;" : "+l"(acc[i][3]) : "l"(qd), "l"(kn3));
                }
            }
        }
        __syncthreads();
    }

    // -- epilogue: store scores, accumulate partial raw sum per b --
    float lambda = __ldg(lam_p);
    float tau = __ldg(tau_p);
    bool v = (n0 + tx * 8) < N_;   // N_ % 8 == 0 -> all-or-nothing per thread
#pragma unroll
    for (int i = 0; i < 8; i++) {
        int b = ty * 8 + i;
        union { unsigned long long u; float2 f; } p0, p1, p2, p3;
        p0.u = acc[i][0]; p1.u = acc[i][1]; p2.u = acc[i][2]; p3.u = acc[i][3];
        float rs = 0.f;
        if (v) {
            size_t base = (size_t)b * N_ + n0 + tx * 8;
            *reinterpret_cast<float4*>(&g_s[base]) = make_float4(p0.f.x, p0.f.y, p1.f.x, p1.f.y);
            *reinterpret_cast<float4*>(&g_s[base + 4]) = make_float4(p2.f.x, p2.f.y, p3.f.x, p3.f.y);
            float sv[8] = {p0.f.x, p0.f.y, p1.f.x, p1.f.y, p2.f.x, p2.f.y, p3.f.x, p3.f.y};
#pragma unroll
            for (int j = 0; j < 8; j++) {
                float gg = 1.f / (1.f + __expf(-lambda * (sv[j] - tau)));
                rs += gg * __expf(sv[j]);
            }
        }
#pragma unroll
        for (int off = 16; off > 0; off >>= 1) rs += __shfl_xor_sync(0xFFFFFFFFu, rs, off);
        if (tx == 0) g_rsp[b * 512 + blockIdx.x] = rs;
    }
}

// ---------------- K3a: stage-1 top-32 per (b, chunk) ----------------------
__device__ __forceinline__ unsigned flipf(float f) {
    unsigned u = __float_as_uint(f);
    return (u & 0x80000000u) ? ~u : (u | 0x80000000u);
}
__device__ __forceinline__ float unflipf(unsigned u) {
    return __uint_as_float((u & 0x80000000u) ? (u & 0x7FFFFFFFu) : ~u);
}

__global__ void __launch_bounds__(256) k_top1() {
    __shared__ unsigned long long sh_cand[256];
    int b = blockIdx.y, c = blockIdx.x;
    int tid = threadIdx.x;
    int lane = tid & 31;
    const float* srow = g_s + (size_t)b * N_ + c * CHSZ;

    unsigned long long list = 0ull;
    const int ITERS = (CHSZ + 255) / 256;  // 25
    for (int it = 0; it < ITERS; it++) {
        int n = tid + it * 256;
        unsigned long long key = 0ull;
        if (n < CHSZ) {
            float sv = srow[n];
            unsigned gn = (unsigned)(c * CHSZ + n);
            key = ((unsigned long long)flipf(sv) << 32) |
                  (unsigned long long)(0xFFFFFFFFu - gn);
        }
        unsigned long long cm = __shfl_sync(0xFFFFFFFFu, list, 0);
        unsigned m = __ballot_sync(0xFFFFFFFFu, key > cm);
        while (m) {
            int src = __ffs(m) - 1;
            unsigned long long kk = __shfl_sync(0xFFFFFFFFu, key, src);
            cm = __shfl_sync(0xFFFFFFFFu, list, 0);
            if (kk > cm) {
                unsigned lt = __ballot_sync(0xFFFFFFFFu, list < kk);
                int pos = __popc(lt);
                unsigned long long dn = __shfl_down_sync(0xFFFFFFFFu, list, 1);
                if (lane < pos - 1) list = dn;
                else if (lane == pos - 1) list = kk;
            }
            m &= m - 1;
        }
    }
    sh_cand[tid] = list;
    __syncthreads();

    if (tid < 32) {
        unsigned long long cc[8];
#pragma unroll
        for (int i = 0; i < 8; i++) cc[i] = sh_cand[i * 32 + lane];
        for (int round = 0; round < 32; round++) {
            unsigned long long lm = cc[0];
#pragma unroll
            for (int i = 1; i < 8; i++) lm = (cc[i] > lm) ? cc[i] : lm;
            unsigned long long mm = lm;
#pragma unroll
            for (int off = 16; off > 0; off >>= 1) {
                unsigned long long o = __shfl_xor_sync(0xFFFFFFFFu, mm, off);
                if (o > mm) mm = o;
            }
            unsigned has = __ballot_sync(0xFFFFFFFFu, lm == mm);
            int src = __ffs(has) - 1;
            if (lane == src) {
#pragma unroll
                for (int i = 0; i < 8; i++)
                    if (cc[i] == mm) cc[i] = 0ull;
            }
            if (lane == round)
                g_cand[(b * NCHK + c) * KMAX + round] = mm;
        }
    }
}

// ---------------- K3b: stage-2 merge + alpha --------------------------------
__global__ void __launch_bounds__(32) k_top2(const float* __restrict__ tau_p,
                                             const float* __restrict__ lam_p,
                                             const int* __restrict__ warm_p,
                                             int has_warm,
                                             float* __restrict__ out,
                                             int out_size,
                                             int nblk) {
    int b = blockIdx.x;
    int lane = threadIdx.x;
    float lambda = __ldg(lam_p);
    float tau = __ldg(tau_p);

    unsigned long long cc[NCHK];
#pragma unroll
    for (int j = 0; j < NCHK; j++)
        cc[j] = g_cand[b * NCHK * KMAX + j * 32 + lane];

    // deterministic raw-sum reduction over score-GEMM block partials
    float rsum = 0.f;
    for (int j = lane; j < nblk; j += 32) rsum += g_rsp[b * 512 + j];
#pragma unroll
    for (int off = 16; off > 0; off >>= 1) rsum += __shfl_xor_sync(0xFFFFFFFFu, rsum, off);

    float myS = 0.f;
    int myN = 0;
    for (int round = 0; round < 32; round++) {
        unsigned long long lm = cc[0];
#pragma unroll
        for (int i = 1; i < NCHK; i++) lm = (cc[i] > lm) ? cc[i] : lm;
        unsigned long long mm = lm;
#pragma unroll
        for (int off = 16; off > 0; off >>= 1) {
            unsigned long long o = __shfl_xor_sync(0xFFFFFFFFu, mm, off);
            if (o > mm) mm = o;
        }
        unsigned has = __ballot_sync(0xFFFFFFFFu, lm == mm);
        int src = __ffs(has) - 1;
        if (lane == src) {
#pragma unroll
            for (int i = 0; i < NCHK; i++)
                if (cc[i] == mm) cc[i] = 0ull;
        }
        if (lane == round) {
            unsigned hi = (unsigned)(mm >> 32);
            unsigned lo = (unsigned)(mm & 0xFFFFFFFFu);
            myS = unflipf(hi);
            myN = (int)(0xFFFFFFFFu - lo);
        }
    }

    int warm = has_warm ? __ldg(warm_p) : 0;
    float alpha;
    if (warm) {
        float smax = __shfl_sync(0xFFFFFFFFu, myS, 0);
        float e = expf(myS - smax);
        float den = e;
#pragma unroll
        for (int off = 16; off > 0; off >>= 1) den += __shfl_xor_sync(0xFFFFFFFFu, den, off);
        alpha = e / den;
    } else {
        float x = lambda * (myS - tau);
        float gg = 1.f / (1.f + expf(-x));
        float r = gg * expf(myS);
        float nr = r / (rsum + EPSF);
        float snr = nr;
#pragma unroll
        for (int off = 16; off > 0; off >>= 1) snr += __shfl_xor_sync(0xFFFFFFFFu, snr, off);
        alpha = nr / (snr + EPSF);
    }
    out[b * KMAX + lane] = alpha;
    if (out_size >= 2 * B_ * KMAX)
        out[B_ * KMAX + b * KMAX + lane] = (float)myN;
}

// ---------------- host launch ----------------
extern "C" void kernel_launch(void* const* d_in, const int* in_sizes, int n_in,
                              void* d_out, int out_size) {
    const float* z    = (const float*)d_in[0];   // [64,2048]
    const float* keys = (const float*)d_in[1];   // [8,100000,64]
    const float* wq   = (const float*)d_in[2];   // [8,64,2048]
    const float* aw   = (const float*)d_in[3];   // [8]
    const float* tau  = (const float*)d_in[4];   // scalar
    const float* lam  = (const float*)d_in[5];   // scalar
    const int* warm   = (n_in > 6) ? (const int*)d_in[6] : nullptr;

    k_proj_partial<<<dim3(16, 8), 256>>>(z, wq);
    k_proj_reduce<<<128, 256>>>();
    k_qnorm<<<64, 256>>>(aw);

    const int smem2 = (64 * TNB + 64 * 64) * 4;  // 80KB
    cudaFuncSetAttribute(k_scores2, cudaFuncAttributeMaxDynamicSharedMemorySize, smem2);
    int nblk = (N_ + TNB - 1) / TNB;  // 391
    k_scores2<<<nblk, 256, smem2>>>(keys, tau, lam);

    k_top1<<<dim3(NCHK, B_), 256>>>();
    k_top2<<<B_, 32>>>(tau, lam, warm, warm != nullptr, (float*)d_out, out_size, nblk);
}

// round 4
// speedup vs baseline: 2.5330x; 1.7550x over previous
#include <cuda_runtime.h>
#include <cuda_bf16.h>
#include <math.h>
#include <stdint.h>

// Problem constants (fixed by setup_inputs)
#define B_   64
#define S_   8
#define DK_  64
#define DA_  2048
#define N_   100000
#define KTOT 512        // S_*DK_
#define KMAX 32
#define NCHK 16         // top-k stage-1 chunks
#define CHSZ (N_ / NCHK) // 6250
#define NTILES ((N_ + 127) / 128)   // 782
#define EPSF 1e-8f

// padded bf16 row strides (bytes)
#define KSROW 144       // 64 bf16 + 8 pad  -> 16B shift/row (conflict-free)
#define QSROW 1040      // 512 bf16 + 8 pad -> 16B shift/row
#define SM_KS 0
#define SM_QS (128 * KSROW)                 // 18432
#define SM_TOTAL (SM_QS + 64 * QSROW)       // 18432 + 66560 = 84992

// ---------------- device scratch ----------------
__device__ float g_qpart[16 * B_ * KTOT];
__device__ float g_q[B_ * KTOT];
__device__ float g_qhat[B_ * KTOT];                       // fp32 q̂ (exact rescore)
__device__ __align__(16) __nv_bfloat16 g_qbf[B_ * KTOT];  // bf16 q̂ (MMA operand)
__device__ float g_s[(size_t)B_ * N_];                    // approx scores [b][n]
__device__ float g_rsp[B_ * NCHK];                        // rsum partials
__device__ unsigned long long g_cand[B_ * NCHK * KMAX];   // stage-1 approx cands
__device__ unsigned long long g_cand2[B_ * 64];           // merged top-64 approx
__device__ unsigned long long g_cexact[B_ * 64];          // rescored exact keys

// ================= helpers =================
__device__ __forceinline__ uint32_t smem_u32(const void* p) {
    uint32_t a;
    asm("{ .reg .u64 t; cvta.to.shared.u64 t, %1; cvt.u32.u64 %0, t; }" : "=r"(a) : "l"(p));
    return a;
}
__device__ __forceinline__ void ldsm_x4(uint32_t& r0, uint32_t& r1, uint32_t& r2,
                                        uint32_t& r3, uint32_t addr) {
    asm volatile("ldmatrix.sync.aligned.m8n8.x4.shared.b16 {%0,%1,%2,%3}, [%4];"
                 : "=r"(r0), "=r"(r1), "=r"(r2), "=r"(r3) : "r"(addr));
}
__device__ __forceinline__ void mma16816(float* c, const uint32_t* a,
                                         uint32_t b0, uint32_t b1) {
    asm volatile(
        "mma.sync.aligned.m16n8k16.row.col.f32.bf16.bf16.f32 "
        "{%0,%1,%2,%3}, {%4,%5,%6,%7}, {%8,%9}, {%0,%1,%2,%3};"
        : "+f"(c[0]), "+f"(c[1]), "+f"(c[2]), "+f"(c[3])
        : "r"(a[0]), "r"(a[1]), "r"(a[2]), "r"(a[3]), "r"(b0), "r"(b1));
}

// ---------------- K1a: query projection partial GEMM ----------------
__global__ void __launch_bounds__(256) k_proj_partial(const float* __restrict__ z,
                                                      const float* __restrict__ wq) {
    __shared__ float zt[64][33];
    __shared__ float wt[64][33];
    int tid = threadIdx.x;
    int tx = tid & 15, ty = tid >> 4;
    int a_base = blockIdx.x * 128;
    int sk_base = blockIdx.y * 64;
    float acc[4][4] = {};
    for (int t = 0; t < 4; t++) {
        int a0 = a_base + t * 32;
        for (int idx = tid; idx < 64 * 32; idx += 256) {
            int r = idx >> 5, c = idx & 31;
            zt[r][c] = z[r * DA_ + a0 + c];
            wt[r][c] = wq[(size_t)(sk_base + r) * DA_ + a0 + c];
        }
        __syncthreads();
#pragma unroll
        for (int a = 0; a < 32; a++) {
            float zv[4], wv[4];
#pragma unroll
            for (int i = 0; i < 4; i++) zv[i] = zt[4 * ty + i][a];
#pragma unroll
            for (int j = 0; j < 4; j++) wv[j] = wt[4 * tx + j][a];
#pragma unroll
            for (int i = 0; i < 4; i++)
#pragma unroll
                for (int j = 0; j < 4; j++) acc[i][j] += zv[i] * wv[j];
        }
        __syncthreads();
    }
#pragma unroll
    for (int i = 0; i < 4; i++)
#pragma unroll
        for (int j = 0; j < 4; j++)
            g_qpart[blockIdx.x * (B_ * KTOT) + (4 * ty + i) * KTOT + sk_base + 4 * tx + j] = acc[i][j];
}

__global__ void k_proj_reduce() {
    int idx = blockIdx.x * blockDim.x + threadIdx.x;
    if (idx < B_ * KTOT) {
        float s = 0.f;
#pragma unroll
        for (int p = 0; p < 16; p++) s += g_qpart[p * (B_ * KTOT) + idx];
        g_q[idx] = s;
    }
}

// ---------------- K1b: normalize q, fold softmax(aw), emit fp32+bf16 ------
__global__ void k_qnorm(const float* __restrict__ aw) {
    int gw = (blockIdx.x * blockDim.x + threadIdx.x) >> 5;
    int lane = threadIdx.x & 31;
    if (gw >= B_ * S_) return;
    int b = gw >> 3, s = gw & 7;
    int base = b * KTOT + s * 64;
    float q0 = g_q[base + lane];
    float q1 = g_q[base + 32 + lane];
    float ss = q0 * q0 + q1 * q1;
#pragma unroll
    for (int off = 16; off > 0; off >>= 1) ss += __shfl_xor_sync(0xFFFFFFFFu, ss, off);
    float m = aw[0];
#pragma unroll
    for (int i = 1; i < 8; i++) m = fmaxf(m, aw[i]);
    float den = 0.f, es = 0.f;
#pragma unroll
    for (int i = 0; i < 8; i++) {
        float e = expf(aw[i] - m);
        den += e;
        if (i == s) es = e;
    }
    float wsm = es / den;
    float scale = wsm / (sqrtf(ss) + EPSF);
    float h0 = q0 * scale, h1 = q1 * scale;
    g_qhat[base + lane] = h0;
    g_qhat[base + 32 + lane] = h1;
    g_qbf[base + lane] = __float2bfloat16(h0);
    g_qbf[base + 32 + lane] = __float2bfloat16(h1);
}

// ---------------- K2: bf16 HMMA score GEMM (mma.sync m16n8k16) -------------
// One CTA per 128-n tile. 8 warps: wb = wid&3 (16 b rows), wn = wid>>2 (64 n).
// Per aspect: LDG fp32 keys (2 thr/row), fold inv-norm into bf16 STS, then
// ldmatrix + mma accumulate. Epilogue: fp32 accums -> g_s[b][n].
__global__ void __launch_bounds__(256, 2) k_mma(const float* __restrict__ keys) {
    extern __shared__ char smem[];
    uint32_t sb = smem_u32(smem);
    int tid = threadIdx.x;
    int wid = tid >> 5, lane = tid & 31;
    int wb = wid & 3, wn = wid >> 2;
    int n0 = blockIdx.x * 128;

    // ---- stage q̂ bf16 into padded smem: qs[64 b][512 k] rows of QSROW ----
    {
        const uint4* src = reinterpret_cast<const uint4*>(g_qbf);
        for (int i = tid; i < 64 * 64; i += 256) {
            int row = i >> 6, j = i & 63;
            uint4 v = src[row * 64 + j];
            *reinterpret_cast<uint4*>(smem + SM_QS + row * QSROW + j * 16) = v;
        }
    }

    int r = tid >> 1, hf = tid & 1;            // key load: 2 threads / n-row
    int nrow = n0 + r;
    if (nrow >= N_) nrow = N_ - 1;

    float acc[8][4] = {};                       // 8 n-groups x 4 fp32
    float4 v[8];
    {
        const float4* src = reinterpret_cast<const float4*>(
            keys + ((size_t)nrow) * DK_ + hf * 32);
#pragma unroll
        for (int j = 0; j < 8; j++) v[j] = __ldg(src + j);
    }

    // ldmatrix lane addresses (constant parts)
    int a_row = wb * 16 + (lane & 7) + ((lane >> 3) & 1) * 8;
    int a_kof = (lane >> 4) * 8;               // +0 or +8 within k-chunk
    int b_rowlane = wn * 64 + (lane & 7);      // within-tile n row base (plus ng*8)
    int b_kof = (lane >> 3) * 8;               // 0,8,16,24

    for (int s = 0; s < S_; s++) {
        // norm over the full 64-float row (pairs share via shfl)
        float ssv = 0.f;
#pragma unroll
        for (int j = 0; j < 8; j++)
            ssv += v[j].x * v[j].x + v[j].y * v[j].y + v[j].z * v[j].z + v[j].w * v[j].w;
        ssv += __shfl_xor_sync(0xFFFFFFFFu, ssv, 1);
        float inv = 1.f / (sqrtf(ssv) + EPSF);

        __syncthreads();   // previous aspect's ldmatrix readers done

        // STS normalized bf16: ks[r][hf*32 .. +31]
        char* rowp = smem + SM_KS + r * KSROW + hf * 64;
#pragma unroll
        for (int j = 0; j < 4; j++) {
            float4 a = v[2 * j], b4 = v[2 * j + 1];
            __nv_bfloat162 p0 = __float22bfloat162_rn(make_float2(a.x * inv, a.y * inv));
            __nv_bfloat162 p1 = __float22bfloat162_rn(make_float2(a.z * inv, a.w * inv));
            __nv_bfloat162 p2 = __float22bfloat162_rn(make_float2(b4.x * inv, b4.y * inv));
            __nv_bfloat162 p3 = __float22bfloat162_rn(make_float2(b4.z * inv, b4.w * inv));
            uint4 pk;
            pk.x = *reinterpret_cast<uint32_t*>(&p0);
            pk.y = *reinterpret_cast<uint32_t*>(&p1);
            pk.z = *reinterpret_cast<uint32_t*>(&p2);
            pk.w = *reinterpret_cast<uint32_t*>(&p3);
            *reinterpret_cast<uint4*>(rowp + j * 16) = pk;
        }
        __syncthreads();   // ks ready

        // prefetch next aspect's keys (hide LDG under mma)
        if (s < S_ - 1) {
            const float4* src = reinterpret_cast<const float4*>(
                keys + ((size_t)(s + 1) * N_ + nrow) * DK_ + hf * 32);
#pragma unroll
            for (int j = 0; j < 8; j++) v[j] = __ldg(src + j);
        }

        // A fragments for this aspect: 4 k-chunks
        uint32_t afr[4][4];
#pragma unroll
        for (int kc = 0; kc < 4; kc++) {
            uint32_t addr = sb + SM_QS + a_row * QSROW + (s * 64 + kc * 16 + a_kof) * 2;
            ldsm_x4(afr[kc][0], afr[kc][1], afr[kc][2], afr[kc][3], addr);
        }

        // B fragments + mma over 8 n-groups
#pragma unroll
        for (int ng = 0; ng < 8; ng++) {
            uint32_t baddr = sb + SM_KS + (b_rowlane + ng * 8) * KSROW + b_kof * 2;
            uint32_t bb[8];
            ldsm_x4(bb[0], bb[1], bb[2], bb[3], baddr);
            ldsm_x4(bb[4], bb[5], bb[6], bb[7], baddr + 64);  // +32 elems
#pragma unroll
            for (int kc = 0; kc < 4; kc++)
                mma16816(acc[ng], afr[kc], bb[kc * 2], bb[kc * 2 + 1]);
        }
    }

    // ---- epilogue: acc -> g_s[b][n] ----
    int brow = wb * 16 + (lane >> 2);
    int ncol0 = n0 + wn * 64 + 2 * (lane & 3);
#pragma unroll
    for (int ng = 0; ng < 8; ng++) {
        int n = ncol0 + ng * 8;
        if (n < N_) {
            *reinterpret_cast<float2*>(&g_s[(size_t)brow * N_ + n]) =
                make_float2(acc[ng][0], acc[ng][1]);
            *reinterpret_cast<float2*>(&g_s[(size_t)(brow + 8) * N_ + n]) =
                make_float2(acc[ng][2], acc[ng][3]);
        }
    }
}

// ---------------- poly rsum term (no MUFU; tolerance ~1%) ------------------
__device__ __forceinline__ float rsum_term(float s, float lambda, float tau) {
    float e = 1.f + s * (1.f + s * (0.5f + s * (0.16666667f + s * (0.041666667f + s * 0.0083333333f))));
    float x = lambda * (s - tau);
    float ax = fabsf(x);
    float t;
    if (ax >= 4.5f) {
        t = 1.f;
    } else {
        float y = 0.5f * ax, y2 = y * y;
        float num = y * (27.f + y2);
        float den = fmaf(9.f, y2, 27.f);
        float rc = fmaf(den, -5.10e-4f, 0.05081f);
        rc = rc * (2.f - den * rc);
        rc = rc * (2.f - den * rc);
        t = fminf(num * rc, 1.f);
    }
    float g = fmaf(copysignf(t, x), 0.5f, 0.5f);
    return g * e;
}

__device__ __forceinline__ unsigned flipf(float f) {
    unsigned u = __float_as_uint(f);
    return (u & 0x80000000u) ? ~u : (u | 0x80000000u);
}
__device__ __forceinline__ float unflipf(unsigned u) {
    return __uint_as_float((u & 0x80000000u) ? (u & 0x7FFFFFFFu) : ~u);
}

// ---------------- K3a: stage-1 approx top-32 per (b, chunk) + rsum ---------
__global__ void __launch_bounds__(256) k_top1(const float* __restrict__ tau_p,
                                              const float* __restrict__ lam_p) {
    __shared__ unsigned long long sh_cand[256];
    __shared__ float sh_rs[8];
    int b = blockIdx.y, c = blockIdx.x;
    int tid = threadIdx.x;
    int lane = tid & 31, wid = tid >> 5;
    float lambda = __ldg(lam_p), tau = __ldg(tau_p);
    const float* srow = g_s + (size_t)b * N_ + c * CHSZ;

    unsigned long long list = 0ull;
    float rs = 0.f;
    const int ITERS = (CHSZ + 255) / 256;
    for (int it = 0; it < ITERS; it++) {
        int n = tid + it * 256;
        unsigned long long key = 0ull;
        if (n < CHSZ) {
            float sv = srow[n];
            rs += rsum_term(sv, lambda, tau);
            unsigned gn = (unsigned)(c * CHSZ + n);
            key = ((unsigned long long)flipf(sv) << 32) |
                  (unsigned long long)(0xFFFFFFFFu - gn);
        }
        unsigned long long cm = __shfl_sync(0xFFFFFFFFu, list, 0);
        unsigned m = __ballot_sync(0xFFFFFFFFu, key > cm);
        while (m) {
            int src = __ffs(m) - 1;
            unsigned long long kk = __shfl_sync(0xFFFFFFFFu, key, src);
            cm = __shfl_sync(0xFFFFFFFFu, list, 0);
            if (kk > cm) {
                unsigned lt = __ballot_sync(0xFFFFFFFFu, list < kk);
                int pos = __popc(lt);
                unsigned long long dn = __shfl_down_sync(0xFFFFFFFFu, list, 1);
                if (lane < pos - 1) list = dn;
                else if (lane == pos - 1) list = kk;
            }
            m &= m - 1;
        }
    }
    sh_cand[tid] = list;
#pragma unroll
    for (int off = 16; off > 0; off >>= 1) rs += __shfl_xor_sync(0xFFFFFFFFu, rs, off);
    if (lane == 0) sh_rs[wid] = rs;
    __syncthreads();

    if (tid == 0) {
        float tot = 0.f;
#pragma unroll
        for (int i = 0; i < 8; i++) tot += sh_rs[i];
        g_rsp[b * NCHK + c] = tot;
    }
    if (tid < 32) {
        unsigned long long cc[8];
#pragma unroll
        for (int i = 0; i < 8; i++) cc[i] = sh_cand[i * 32 + lane];
        for (int round = 0; round < 32; round++) {
            unsigned long long lm = cc[0];
#pragma unroll
            for (int i = 1; i < 8; i++) lm = (cc[i] > lm) ? cc[i] : lm;
            unsigned long long mm = lm;
#pragma unroll
            for (int off = 16; off > 0; off >>= 1) {
                unsigned long long o = __shfl_xor_sync(0xFFFFFFFFu, mm, off);
                if (o > mm) mm = o;
            }
            unsigned has = __ballot_sync(0xFFFFFFFFu, lm == mm);
            int src = __ffs(has) - 1;
            if (lane == src) {
#pragma unroll
                for (int i = 0; i < 8; i++)
                    if (cc[i] == mm) cc[i] = 0ull;
            }
            if (lane == round)
                g_cand[(b * NCHK + c) * KMAX + round] = mm;
        }
    }
}

// ---------------- K3b: merge 16x32 -> top-64 approx candidates -------------
__global__ void __launch_bounds__(32) k_merge64() {
    int b = blockIdx.x;
    int lane = threadIdx.x;
    unsigned long long cc[NCHK];
#pragma unroll
    for (int j = 0; j < NCHK; j++)
        cc[j] = g_cand[b * NCHK * KMAX + j * 32 + lane];
    for (int round = 0; round < 64; round++) {
        unsigned long long lm = cc[0];
#pragma unroll
        for (int i = 1; i < NCHK; i++) lm = (cc[i] > lm) ? cc[i] : lm;
        unsigned long long mm = lm;
#pragma unroll
        for (int off = 16; off > 0; off >>= 1) {
            unsigned long long o = __shfl_xor_sync(0xFFFFFFFFu, mm, off);
            if (o > mm) mm = o;
        }
        unsigned has = __ballot_sync(0xFFFFFFFFu, lm == mm);
        int src = __ffs(has) - 1;
        if (lane == src) {
#pragma unroll
            for (int i = 0; i < NCHK; i++)
                if (cc[i] == mm) cc[i] = 0ull;
        }
        if (lane == 0) g_cand2[b * 64 + round] = mm;
    }
}

// ---------------- K3c: exact fp32 rescore of 64 candidates per row ---------
__global__ void __launch_bounds__(256) k_rescore(const float* __restrict__ keys) {
    int b = blockIdx.y;
    int wid = threadIdx.x >> 5, lane = threadIdx.x & 31;
    int ci = blockIdx.x * 8 + wid;      // 0..63
    unsigned long long key = g_cand2[b * 64 + ci];
    unsigned n = 0xFFFFFFFFu - (unsigned)(key & 0xFFFFFFFFu);

    float stot = 0.f;
#pragma unroll
    for (int s = 0; s < S_; s++) {
        float2 kv = *reinterpret_cast<const float2*>(keys + ((size_t)s * N_ + n) * DK_ + 2 * lane);
        float2 qv = *reinterpret_cast<const float2*>(g_qhat + b * KTOT + s * 64 + 2 * lane);
        float ss = kv.x * kv.x + kv.y * kv.y;
        float dt = kv.x * qv.x + kv.y * qv.y;
#pragma unroll
        for (int off = 16; off > 0; off >>= 1) {
            ss += __shfl_xor_sync(0xFFFFFFFFu, ss, off);
            dt += __shfl_xor_sync(0xFFFFFFFFu, dt, off);
        }
        stot += dt / (sqrtf(ss) + EPSF);
    }
    if (lane == 0)
        g_cexact[b * 64 + ci] = ((unsigned long long)flipf(stot) << 32) |
                                (unsigned long long)(0xFFFFFFFFu - n);
}

// ---------------- K3d: final top-32 + alpha --------------------------------
__global__ void __launch_bounds__(32) k_final(const float* __restrict__ tau_p,
                                              const float* __restrict__ lam_p,
                                              const int* __restrict__ warm_p,
                                              int has_warm,
                                              float* __restrict__ out,
                                              int out_size) {
    int b = blockIdx.x;
    int lane = threadIdx.x;
    float lambda = __ldg(lam_p), tau = __ldg(tau_p);

    unsigned long long cc[2];
    cc[0] = g_cexact[b * 64 + lane];
    cc[1] = g_cexact[b * 64 + 32 + lane];

    float rsum = 0.f;
    if (lane < NCHK) rsum = g_rsp[b * NCHK + lane];
#pragma unroll
    for (int off = 16; off > 0; off >>= 1) rsum += __shfl_xor_sync(0xFFFFFFFFu, rsum, off);

    float myS = 0.f;
    int myN = 0;
    for (int round = 0; round < 32; round++) {
        unsigned long long lm = (cc[0] > cc[1]) ? cc[0] : cc[1];
        unsigned long long mm = lm;
#pragma unroll
        for (int off = 16; off > 0; off >>= 1) {
            unsigned long long o = __shfl_xor_sync(0xFFFFFFFFu, mm, off);
            if (o > mm) mm = o;
        }
        unsigned has = __ballot_sync(0xFFFFFFFFu, lm == mm);
        int src = __ffs(has) - 1;
        if (lane == src) {
            if (cc[0] == mm) cc[0] = 0ull;
            else if (cc[1] == mm) cc[1] = 0ull;
        }
        if (lane == round) {
            myS = unflipf((unsigned)(mm >> 32));
            myN = (int)(0xFFFFFFFFu - (unsigned)(mm & 0xFFFFFFFFu));
        }
    }

    int warm = has_warm ? __ldg(warm_p) : 0;
    float alpha;
    if (warm) {
        float smax = __shfl_sync(0xFFFFFFFFu, myS, 0);
        float e = expf(myS - smax);
        float den = e;
#pragma unroll
        for (int off = 16; off > 0; off >>= 1) den += __shfl_xor_sync(0xFFFFFFFFu, den, off);
        alpha = e / den;
    } else {
        float x = lambda * (myS - tau);
        float gg = 1.f / (1.f + expf(-x));
        float r = gg * expf(myS);
        float nr = r / (rsum + EPSF);
        float snr = nr;
#pragma unroll
        for (int off = 16; off > 0; off >>= 1) snr += __shfl_xor_sync(0xFFFFFFFFu, snr, off);
        alpha = nr / (snr + EPSF);
    }
    out[b * KMAX + lane] = alpha;
    if (out_size >= 2 * B_ * KMAX)
        out[B_ * KMAX + b * KMAX + lane] = (float)myN;
}

// ---------------- host launch ----------------
extern "C" void kernel_launch(void* const* d_in, const int* in_sizes, int n_in,
                              void* d_out, int out_size) {
    const float* z    = (const float*)d_in[0];   // [64,2048]
    const float* keys = (const float*)d_in[1];   // [8,100000,64]
    const float* wq   = (const float*)d_in[2];   // [8,64,2048]
    const float* aw   = (const float*)d_in[3];   // [8]
    const float* tau  = (const float*)d_in[4];   // scalar
    const float* lam  = (const float*)d_in[5];   // scalar
    const int* warm   = (n_in > 6) ? (const int*)d_in[6] : nullptr;

    k_proj_partial<<<dim3(16, 8), 256>>>(z, wq);
    k_proj_reduce<<<128, 256>>>();
    k_qnorm<<<64, 256>>>(aw);

    cudaFuncSetAttribute(k_mma, cudaFuncAttributeMaxDynamicSharedMemorySize, SM_TOTAL);
    k_mma<<<NTILES, 256, SM_TOTAL>>>(keys);

    k_top1<<<dim3(NCHK, B_), 256>>>(tau, lam);
    k_merge64<<<B_, 32>>>();
    k_rescore<<<dim3(8, B_), 256>>>(keys);
    k_final<<<B_, 32>>>(tau, lam, warm, warm != nullptr, (float*)d_out, out_size);
}

// round 5
// speedup vs baseline: 2.7616x; 1.0902x over previous
#include <cuda_runtime.h>
#include <cuda_bf16.h>
#include <math.h>
#include <stdint.h>

// Problem constants (fixed by setup_inputs)
#define B_   64
#define S_   8
#define DK_  64
#define DA_  2048
#define N_   100000
#define KTOT 512        // S_*DK_
#define KMAX 32
#define NT   782        // n-tiles of 128
#define CAP  2048       // candidate buffer per b
#define DELTA 4e-3f     // threshold safety margin (>> bf16 score noise)
#define EPSF 1e-8f

// padded bf16 row strides (bytes)
#define KSROW 144                 // 64 bf16 + 8 pad
#define KSBUF (128 * KSROW)       // 18432 per buffer
#define SM_QS (2 * KSBUF)         // 36864
#define SM_TOTAL (SM_QS + 64 * 1040)  // + q̂ rows: 103424

// ---------------- device scratch ----------------
__device__ float g_qpart[16 * B_ * KTOT];
__device__ float g_q[B_ * KTOT];
__device__ float g_qhat[B_ * KTOT];                       // fp32 q̂ (exact rescore)
__device__ __align__(16) __nv_bfloat16 g_qbf[B_ * KTOT];  // bf16 q̂ (MMA operand)
__device__ float g_s[(size_t)B_ * N_];                    // approx scores [b][n]
__device__ float g_rsp[B_ * NT];                          // rsum partials per (b,tile)
__device__ float g_bmax[B_ * NT];                         // per-(b,tile) max
__device__ float g_T[B_];                                 // collect threshold
__device__ float g_rsum[B_];                              // reduced rsum
__device__ int   g_ccnt[B_];                              // candidate counts
__device__ unsigned long long g_cbuf[B_ * CAP];           // candidates

// ================= helpers =================
__device__ __forceinline__ uint32_t smem_u32(const void* p) {
    uint32_t a;
    asm("{ .reg .u64 t; cvta.to.shared.u64 t, %1; cvt.u32.u64 %0, t; }" : "=r"(a) : "l"(p));
    return a;
}
__device__ __forceinline__ void ldsm_x4(uint32_t& r0, uint32_t& r1, uint32_t& r2,
                                        uint32_t& r3, uint32_t addr) {
    asm volatile("ldmatrix.sync.aligned.m8n8.x4.shared.b16 {%0,%1,%2,%3}, [%4];"
                 : "=r"(r0), "=r"(r1), "=r"(r2), "=r"(r3) : "r"(addr));
}
__device__ __forceinline__ void mma16816(float* c, const uint32_t* a,
                                         uint32_t b0, uint32_t b1) {
    asm volatile(
        "mma.sync.aligned.m16n8k16.row.col.f32.bf16.bf16.f32 "
        "{%0,%1,%2,%3}, {%4,%5,%6,%7}, {%8,%9}, {%0,%1,%2,%3};"
        : "+f"(c[0]), "+f"(c[1]), "+f"(c[2]), "+f"(c[3])
        : "r"(a[0]), "r"(a[1]), "r"(a[2]), "r"(a[3]), "r"(b0), "r"(b1));
}
__device__ __forceinline__ unsigned flipf(float f) {
    unsigned u = __float_as_uint(f);
    return (u & 0x80000000u) ? ~u : (u | 0x80000000u);
}
__device__ __forceinline__ float unflipf(unsigned u) {
    return __uint_as_float((u & 0x80000000u) ? (u & 0x7FFFFFFFu) : ~u);
}
// 0-MUFU sigmoid(lambda(s-tau)) * exp(s) approximation (rsum only; ~0.1% acc)
__device__ __forceinline__ float rsum_term(float s, float lambda, float tau) {
    float e = 1.f + s * (1.f + s * (0.5f + s * (0.16666667f + s * (0.041666667f + s * 0.0083333333f))));
    float x = lambda * (s - tau);
    float ax = fabsf(x);
    float t;
    if (ax >= 4.5f) {
        t = 1.f;
    } else {
        float y = 0.5f * ax, y2 = y * y;
        float num = y * (27.f + y2);
        float den = fmaf(9.f, y2, 27.f);
        float rc = fmaf(den, -5.10e-4f, 0.05081f);
        rc = rc * (2.f - den * rc);
        rc = rc * (2.f - den * rc);
        t = fminf(num * rc, 1.f);
    }
    float g = fmaf(copysignf(t, x), 0.5f, 0.5f);
    return g * e;
}

// ---------------- K1a: query projection partial GEMM ----------------
__global__ void __launch_bounds__(256) k_proj_partial(const float* __restrict__ z,
                                                      const float* __restrict__ wq) {
    __shared__ float zt[64][33];
    __shared__ float wt[64][33];
    int tid = threadIdx.x;
    int tx = tid & 15, ty = tid >> 4;
    int a_base = blockIdx.x * 128;
    int sk_base = blockIdx.y * 64;
    float acc[4][4] = {};
    for (int t = 0; t < 4; t++) {
        int a0 = a_base + t * 32;
        for (int idx = tid; idx < 64 * 32; idx += 256) {
            int r = idx >> 5, c = idx & 31;
            zt[r][c] = z[r * DA_ + a0 + c];
            wt[r][c] = wq[(size_t)(sk_base + r) * DA_ + a0 + c];
        }
        __syncthreads();
#pragma unroll
        for (int a = 0; a < 32; a++) {
            float zv[4], wv[4];
#pragma unroll
            for (int i = 0; i < 4; i++) zv[i] = zt[4 * ty + i][a];
#pragma unroll
            for (int j = 0; j < 4; j++) wv[j] = wt[4 * tx + j][a];
#pragma unroll
            for (int i = 0; i < 4; i++)
#pragma unroll
                for (int j = 0; j < 4; j++) acc[i][j] += zv[i] * wv[j];
        }
        __syncthreads();
    }
#pragma unroll
    for (int i = 0; i < 4; i++)
#pragma unroll
        for (int j = 0; j < 4; j++)
            g_qpart[blockIdx.x * (B_ * KTOT) + (4 * ty + i) * KTOT + sk_base + 4 * tx + j] = acc[i][j];
}

__global__ void k_proj_reduce() {
    int idx = blockIdx.x * blockDim.x + threadIdx.x;
    if (idx < B_ * KTOT) {
        float s = 0.f;
#pragma unroll
        for (int p = 0; p < 16; p++) s += g_qpart[p * (B_ * KTOT) + idx];
        g_q[idx] = s;
    }
}

// ---------------- K1b: normalize q, fold softmax(aw), emit fp32+bf16 ------
__global__ void k_qnorm(const float* __restrict__ aw) {
    int gw = (blockIdx.x * blockDim.x + threadIdx.x) >> 5;
    int lane = threadIdx.x & 31;
    if (gw >= B_ * S_) return;
    int b = gw >> 3, s = gw & 7;
    int base = b * KTOT + s * 64;
    float q0 = g_q[base + lane];
    float q1 = g_q[base + 32 + lane];
    float ss = q0 * q0 + q1 * q1;
#pragma unroll
    for (int off = 16; off > 0; off >>= 1) ss += __shfl_xor_sync(0xFFFFFFFFu, ss, off);
    float m = aw[0];
#pragma unroll
    for (int i = 1; i < 8; i++) m = fmaxf(m, aw[i]);
    float den = 0.f, es = 0.f;
#pragma unroll
    for (int i = 0; i < 8; i++) {
        float e = expf(aw[i] - m);
        den += e;
        if (i == s) es = e;
    }
    float wsm = es / den;
    float scale = wsm / (sqrtf(ss) + EPSF);
    float h0 = q0 * scale, h1 = q1 * scale;
    g_qhat[base + lane] = h0;
    g_qhat[base + 32 + lane] = h1;
    g_qbf[base + lane] = __float2bfloat16(h0);
    g_qbf[base + 32 + lane] = __float2bfloat16(h1);
}

// ---------------- K2: bf16 HMMA score GEMM + fused rsum/blockmax -----------
__global__ void __launch_bounds__(256, 2) k_mma(const float* __restrict__ keys,
                                                const float* __restrict__ tau_p,
                                                const float* __restrict__ lam_p) {
    extern __shared__ char smem[];
    __shared__ float s_rs[2][64];
    __shared__ float s_bm[2][64];
    uint32_t sb = smem_u32(smem);
    int tid = threadIdx.x;
    int wid = tid >> 5, lane = tid & 31;
    int wb = wid & 3, wn = wid >> 2;
    int n0 = blockIdx.x * 128;

    // ---- stage q̂ bf16 into padded smem: qs[64 b][512 k] rows of 1040B ----
    {
        const uint4* src = reinterpret_cast<const uint4*>(g_qbf);
        for (int i = tid; i < 64 * 64; i += 256) {
            int row = i >> 6, j = i & 63;
            uint4 v = src[row * 64 + j];
            *reinterpret_cast<uint4*>(smem + SM_QS + row * 1040 + j * 16) = v;
        }
    }

    int r = tid >> 1, hf = tid & 1;            // key load: 2 threads / n-row
    int nrow = n0 + r;
    if (nrow >= N_) nrow = N_ - 1;

    float acc[8][4] = {};
    float4 v[8];
    {
        const float4* src = reinterpret_cast<const float4*>(
            keys + ((size_t)nrow) * DK_ + hf * 32);
#pragma unroll
        for (int j = 0; j < 8; j++) v[j] = __ldg(src + j);
    }

    int a_row = wb * 16 + (lane & 7) + ((lane >> 3) & 1) * 8;
    int a_kof = (lane >> 4) * 8;
    int b_rowlane = wn * 64 + (lane & 7);
    int b_kof = (lane >> 3) * 8;

    for (int s = 0; s < S_; s++) {
        float ssv = 0.f;
#pragma unroll
        for (int j = 0; j < 8; j++)
            ssv += v[j].x * v[j].x + v[j].y * v[j].y + v[j].z * v[j].z + v[j].w * v[j].w;
        ssv += __shfl_xor_sync(0xFFFFFFFFu, ssv, 1);
        float inv = rsqrtf(ssv);   // approx path only

        uint32_t bufo = (s & 1) * KSBUF;
        char* rowp = smem + bufo + r * KSROW + hf * 64;
#pragma unroll
        for (int j = 0; j < 4; j++) {
            float4 a = v[2 * j], b4 = v[2 * j + 1];
            __nv_bfloat162 p0 = __float22bfloat162_rn(make_float2(a.x * inv, a.y * inv));
            __nv_bfloat162 p1 = __float22bfloat162_rn(make_float2(a.z * inv, a.w * inv));
            __nv_bfloat162 p2 = __float22bfloat162_rn(make_float2(b4.x * inv, b4.y * inv));
            __nv_bfloat162 p3 = __float22bfloat162_rn(make_float2(b4.z * inv, b4.w * inv));
            uint4 pk;
            pk.x = *reinterpret_cast<uint32_t*>(&p0);
            pk.y = *reinterpret_cast<uint32_t*>(&p1);
            pk.z = *reinterpret_cast<uint32_t*>(&p2);
            pk.w = *reinterpret_cast<uint32_t*>(&p3);
            *reinterpret_cast<uint4*>(rowp + j * 16) = pk;
        }
        __syncthreads();   // one barrier per aspect (double-buffered ks)

        if (s < S_ - 1) {
            const float4* src = reinterpret_cast<const float4*>(
                keys + ((size_t)(s + 1) * N_ + nrow) * DK_ + hf * 32);
#pragma unroll
            for (int j = 0; j < 8; j++) v[j] = __ldg(src + j);
        }

        uint32_t afr[4][4];
#pragma unroll
        for (int kc = 0; kc < 4; kc++) {
            uint32_t addr = sb + SM_QS + a_row * 1040 + (s * 64 + kc * 16 + a_kof) * 2;
            ldsm_x4(afr[kc][0], afr[kc][1], afr[kc][2], afr[kc][3], addr);
        }
#pragma unroll
        for (int ng = 0; ng < 8; ng++) {
            uint32_t baddr = sb + bufo + (b_rowlane + ng * 8) * KSROW + b_kof * 2;
            uint32_t bb[8];
            ldsm_x4(bb[0], bb[1], bb[2], bb[3], baddr);
            ldsm_x4(bb[4], bb[5], bb[6], bb[7], baddr + 64);
#pragma unroll
            for (int kc = 0; kc < 4; kc++)
                mma16816(acc[ng], afr[kc], bb[kc * 2], bb[kc * 2 + 1]);
        }
    }

    // ---- epilogue: store scores + fused rsum partial & tile max ----
    float lambda = __ldg(lam_p), tau = __ldg(tau_p);
    int brow = wb * 16 + (lane >> 2);
    int ncol0 = n0 + wn * 64 + 2 * (lane & 3);
    float rs0 = 0.f, rs1 = 0.f, bm0 = -1e30f, bm1 = -1e30f;
#pragma unroll
    for (int ng = 0; ng < 8; ng++) {
        int n = ncol0 + ng * 8;
        if (n < N_) {
            *reinterpret_cast<float2*>(&g_s[(size_t)brow * N_ + n]) =
                make_float2(acc[ng][0], acc[ng][1]);
            *reinterpret_cast<float2*>(&g_s[(size_t)(brow + 8) * N_ + n]) =
                make_float2(acc[ng][2], acc[ng][3]);
            rs0 += rsum_term(acc[ng][0], lambda, tau) + rsum_term(acc[ng][1], lambda, tau);
            rs1 += rsum_term(acc[ng][2], lambda, tau) + rsum_term(acc[ng][3], lambda, tau);
            bm0 = fmaxf(bm0, fmaxf(acc[ng][0], acc[ng][1]));
            bm1 = fmaxf(bm1, fmaxf(acc[ng][2], acc[ng][3]));
        }
    }
#pragma unroll
    for (int off = 1; off <= 2; off <<= 1) {
        rs0 += __shfl_xor_sync(0xFFFFFFFFu, rs0, off);
        rs1 += __shfl_xor_sync(0xFFFFFFFFu, rs1, off);
        bm0 = fmaxf(bm0, __shfl_xor_sync(0xFFFFFFFFu, bm0, off));
        bm1 = fmaxf(bm1, __shfl_xor_sync(0xFFFFFFFFu, bm1, off));
    }
    if ((lane & 3) == 0) {
        s_rs[wn][brow] = rs0; s_rs[wn][brow + 8] = rs1;
        s_bm[wn][brow] = bm0; s_bm[wn][brow + 8] = bm1;
    }
    __syncthreads();
    if (tid < 64) {
        g_rsp[tid * NT + blockIdx.x] = s_rs[0][tid] + s_rs[1][tid];
        g_bmax[tid * NT + blockIdx.x] = fmaxf(s_bm[0][tid], s_bm[1][tid]);
    }
}

// ---------------- K3a: per-b threshold (32nd tile-max - delta) + rsum ------
__global__ void __launch_bounds__(32) k_thresh() {
    int b = blockIdx.x;
    int lane = threadIdx.x;

    float rsum = 0.f;
    for (int i = lane; i < NT; i += 32) rsum += g_rsp[b * NT + i];
#pragma unroll
    for (int off = 16; off > 0; off >>= 1) rsum += __shfl_xor_sync(0xFFFFFFFFu, rsum, off);

    unsigned list = 0u;
    for (int i0 = 0; i0 < NT; i0 += 32) {
        int i = i0 + lane;
        unsigned key = (i < NT) ? flipf(g_bmax[b * NT + i]) : 0u;
        unsigned cm = __shfl_sync(0xFFFFFFFFu, list, 0);
        unsigned m = __ballot_sync(0xFFFFFFFFu, key > cm);
        while (m) {
            int src = __ffs(m) - 1;
            unsigned kk = __shfl_sync(0xFFFFFFFFu, key, src);
            cm = __shfl_sync(0xFFFFFFFFu, list, 0);
            if (kk > cm) {
                unsigned lt = __ballot_sync(0xFFFFFFFFu, list < kk);
                int pos = __popc(lt);
                unsigned dn = __shfl_down_sync(0xFFFFFFFFu, list, 1);
                if (lane < pos - 1) list = dn;
                else if (lane == pos - 1) list = kk;
            }
            m &= m - 1;
        }
    }
    if (lane == 0) {
        g_T[b] = unflipf(list) - DELTA;   // lane 0 holds the 32nd largest
        g_rsum[b] = rsum;
        g_ccnt[b] = 0;
    }
}

// ---------------- K3b: collect candidates >= T[b] ---------------------------
__global__ void __launch_bounds__(256) k_collect() {
    int b = blockIdx.y;
    int tid = threadIdx.x;
    float T = g_T[b];
    const float* srow = g_s + (size_t)b * N_;
    int base = blockIdx.x * 1024;
#pragma unroll
    for (int i = 0; i < 4; i++) {
        int n = base + i * 256 + tid;
        if (n < N_) {
            float sv = srow[n];
            if (sv >= T) {
                int idx = atomicAdd(&g_ccnt[b], 1);
                if (idx < CAP)
                    g_cbuf[b * CAP + idx] =
                        ((unsigned long long)flipf(sv) << 32) |
                        (unsigned long long)(0xFFFFFFFFu - (unsigned)n);
            }
        }
    }
}

// ---------------- K3c: exact rescore + final top-32 + alpha ----------------
__global__ void __launch_bounds__(256) k_sel(const float* __restrict__ keys,
                                             const float* __restrict__ tau_p,
                                             const float* __restrict__ lam_p,
                                             const int* __restrict__ warm_p,
                                             int has_warm,
                                             float* __restrict__ out,
                                             int out_size) {
    __shared__ unsigned long long ex[CAP];
    __shared__ unsigned long long w32[8][32];
    int b = blockIdx.x;
    int tid = threadIdx.x;
    int wid = tid >> 5, lane = tid & 31;
    int cnt = min(g_ccnt[b], CAP);

    // exact fp32 rescore of each candidate (thread-serial per candidate)
    for (int ci = tid; ci < cnt; ci += 256) {
        unsigned long long key = g_cbuf[b * CAP + ci];
        unsigned n = 0xFFFFFFFFu - (unsigned)(key & 0xFFFFFFFFu);
        float stot = 0.f;
#pragma unroll
        for (int s = 0; s < S_; s++) {
            const float4* kp = reinterpret_cast<const float4*>(keys + ((size_t)s * N_ + n) * DK_);
            const float4* qp = reinterpret_cast<const float4*>(g_qhat + b * KTOT + s * 64);
            float ss = 0.f, dt = 0.f;
#pragma unroll
            for (int j = 0; j < 16; j++) {
                float4 kv = __ldg(kp + j);
                float4 qv = qp[j];
                ss += kv.x * kv.x + kv.y * kv.y + kv.z * kv.z + kv.w * kv.w;
                dt += kv.x * qv.x + kv.y * qv.y + kv.z * qv.z + kv.w * qv.w;
            }
            stot += dt / (sqrtf(ss) + EPSF);
        }
        ex[ci] = ((unsigned long long)flipf(stot) << 32) |
                 (unsigned long long)(0xFFFFFFFFu - n);
    }
    __syncthreads();

    // per-warp top-32 over strided slice of exact keys
    unsigned long long list = 0ull;
    for (int base = wid * 32; base < cnt; base += 256) {
        int ci = base + lane;
        unsigned long long key = (ci < cnt) ? ex[ci] : 0ull;
        unsigned long long cm = __shfl_sync(0xFFFFFFFFu, list, 0);
        unsigned m = __ballot_sync(0xFFFFFFFFu, key > cm);
        while (m) {
            int src = __ffs(m) - 1;
            unsigned long long kk = __shfl_sync(0xFFFFFFFFu, key, src);
            cm = __shfl_sync(0xFFFFFFFFu, list, 0);
            if (kk > cm) {
                unsigned lt = __ballot_sync(0xFFFFFFFFu, list < kk);
                int pos = __popc(lt);
                unsigned long long dn = __shfl_down_sync(0xFFFFFFFFu, list, 1);
                if (lane < pos - 1) list = dn;
                else if (lane == pos - 1) list = kk;
            }
            m &= m - 1;
        }
    }
    w32[wid][lane] = list;
    __syncthreads();

    if (wid == 0) {
        float lambda = __ldg(lam_p), tau = __ldg(tau_p);
        unsigned long long cc[8];
#pragma unroll
        for (int i = 0; i < 8; i++) cc[i] = w32[i][lane];

        float myS = 0.f;
        int myN = 0;
        for (int round = 0; round < 32; round++) {
            unsigned long long lm = cc[0];
#pragma unroll
            for (int i = 1; i < 8; i++) lm = (cc[i] > lm) ? cc[i] : lm;
            unsigned long long mm = lm;
#pragma unroll
            for (int off = 16; off > 0; off >>= 1) {
                unsigned long long o = __shfl_xor_sync(0xFFFFFFFFu, mm, off);
                if (o > mm) mm = o;
            }
            unsigned has = __ballot_sync(0xFFFFFFFFu, lm == mm);
            int src = __ffs(has) - 1;
            if (lane == src) {
#pragma unroll
                for (int i = 0; i < 8; i++)
                    if (cc[i] == mm) cc[i] = 0ull;
            }
            if (lane == round) {
                myS = unflipf((unsigned)(mm >> 32));
                myN = (int)(0xFFFFFFFFu - (unsigned)(mm & 0xFFFFFFFFu));
            }
        }

        int warm = has_warm ? __ldg(warm_p) : 0;
        float alpha;
        if (warm) {
            float smax = __shfl_sync(0xFFFFFFFFu, myS, 0);
            float e = expf(myS - smax);
            float den = e;
#pragma unroll
            for (int off = 16; off > 0; off >>= 1) den += __shfl_xor_sync(0xFFFFFFFFu, den, off);
            alpha = e / den;
        } else {
            float rsum = g_rsum[b];
            float x = lambda * (myS - tau);
            float gg = 1.f / (1.f + expf(-x));
            float r = gg * expf(myS);
            float nr = r / (rsum + EPSF);
            float snr = nr;
#pragma unroll
            for (int off = 16; off > 0; off >>= 1) snr += __shfl_xor_sync(0xFFFFFFFFu, snr, off);
            alpha = nr / (snr + EPSF);
        }
        out[b * KMAX + lane] = alpha;
        if (out_size >= 2 * B_ * KMAX)
            out[B_ * KMAX + b * KMAX + lane] = (float)myN;
    }
}

// ---------------- host launch ----------------
extern "C" void kernel_launch(void* const* d_in, const int* in_sizes, int n_in,
                              void* d_out, int out_size) {
    const float* z    = (const float*)d_in[0];   // [64,2048]
    const float* keys = (const float*)d_in[1];   // [8,100000,64]
    const float* wq   = (const float*)d_in[2];   // [8,64,2048]
    const float* aw   = (const float*)d_in[3];   // [8]
    const float* tau  = (const float*)d_in[4];   // scalar
    const float* lam  = (const float*)d_in[5];   // scalar
    const int* warm   = (n_in > 6) ? (const int*)d_in[6] : nullptr;

    k_proj_partial<<<dim3(16, 8), 256>>>(z, wq);
    k_proj_reduce<<<128, 256>>>();
    k_qnorm<<<64, 256>>>(aw);

    cudaFuncSetAttribute(k_mma, cudaFuncAttributeMaxDynamicSharedMemorySize, SM_TOTAL);
    k_mma<<<NT, 256, SM_TOTAL>>>(keys, tau, lam);

    k_thresh<<<B_, 32>>>();
    k_collect<<<dim3(98, B_), 256>>>();
    k_sel<<<B_, 256>>>(keys, tau, lam, warm, warm != nullptr, (float*)d_out, out_size);
}

// round 6
// speedup vs baseline: 3.0459x; 1.1029x over previous
#include <cuda_runtime.h>
#include <cuda_bf16.h>
#include <math.h>
#include <stdint.h>

// Problem constants (fixed by setup_inputs)
#define B_   64
#define S_   8
#define DK_  64
#define DA_  2048
#define N_   100000
#define KTOT 512        // S_*DK_
#define KMAX 32
#define NT   782        // n-tiles of 128
#define CAP  2048       // candidate buffer per b
#define DELTA 4e-3f     // threshold safety margin (>> bf16 score noise)
#define EPSF 1e-8f

// smem layout for k_mma (bytes)
#define STG_STRIDE 288            // 256B fp32 row + split-pad (conflict-free)
#define STG_BUF (128 * STG_STRIDE)   // 36864
#define SM_STG 0                     // 2 bufs: 73728
#define KSROW 144                    // bf16 row: 128B + 16 pad
#define KSBUF (128 * KSROW)          // 18432
#define SM_KS  (2 * STG_BUF)         // 73728; 2 bufs: 36864
#define SM_TOTAL (SM_KS + 2 * KSBUF) // 110592 (108 KB) -> 2 CTAs/SM

// ---------------- device scratch ----------------
__device__ float g_qpart[16 * B_ * KTOT];
__device__ float g_qhat[B_ * KTOT];               // fp32 q̂ (exact rescore)
__device__ uint4 g_qfrag[128 * 32];               // mma A fragments (64 KB)
__device__ float g_s[(size_t)B_ * N_];            // approx scores [b][n]
__device__ float g_rsp[B_ * NT];                  // rsum partials per (b,tile)
__device__ float g_bmax[B_ * NT];                 // per-(b,tile) max
__device__ float g_T[B_];                         // collect threshold
__device__ float g_rsum[B_];                      // reduced rsum
__device__ int   g_ccnt[B_];                      // candidate counts
__device__ unsigned long long g_cbuf[B_ * CAP];   // candidates

// ================= helpers =================
__device__ __forceinline__ uint32_t smem_u32(const void* p) {
    uint32_t a;
    asm("{ .reg .u64 t; cvta.to.shared.u64 t, %1; cvt.u32.u64 %0, t; }" : "=r"(a) : "l"(p));
    return a;
}
__device__ __forceinline__ void cp_async16(uint32_t dst, const void* src) {
    asm volatile("cp.async.cg.shared.global [%0], [%1], 16;" :: "r"(dst), "l"(src));
}
#define CP_COMMIT() asm volatile("cp.async.commit_group;" ::: "memory")
#define CP_WAIT1()  asm volatile("cp.async.wait_group 1;" ::: "memory")
__device__ __forceinline__ void ldsm_x4(uint32_t& r0, uint32_t& r1, uint32_t& r2,
                                        uint32_t& r3, uint32_t addr) {
    asm volatile("ldmatrix.sync.aligned.m8n8.x4.shared.b16 {%0,%1,%2,%3}, [%4];"
                 : "=r"(r0), "=r"(r1), "=r"(r2), "=r"(r3) : "r"(addr));
}
__device__ __forceinline__ void mma16816(float* c, const uint32_t* a,
                                         uint32_t b0, uint32_t b1) {
    asm volatile(
        "mma.sync.aligned.m16n8k16.row.col.f32.bf16.bf16.f32 "
        "{%0,%1,%2,%3}, {%4,%5,%6,%7}, {%8,%9}, {%0,%1,%2,%3};"
        : "+f"(c[0]), "+f"(c[1]), "+f"(c[2]), "+f"(c[3])
        : "r"(a[0]), "r"(a[1]), "r"(a[2]), "r"(a[3]), "r"(b0), "r"(b1));
}
__device__ __forceinline__ unsigned flipf(float f) {
    unsigned u = __float_as_uint(f);
    return (u & 0x80000000u) ? ~u : (u | 0x80000000u);
}
__device__ __forceinline__ float unflipf(unsigned u) {
    return __uint_as_float((u & 0x80000000u) ? (u & 0x7FFFFFFFu) : ~u);
}
// 0-MUFU sigmoid(lambda(s-tau)) * exp(s) approximation (rsum only; ~0.1% acc)
__device__ __forceinline__ float rsum_term(float s, float lambda, float tau) {
    float e = 1.f + s * (1.f + s * (0.5f + s * (0.16666667f + s * (0.041666667f + s * 0.0083333333f))));
    float x = lambda * (s - tau);
    float ax = fabsf(x);
    float t;
    if (ax >= 4.5f) {
        t = 1.f;
    } else {
        float y = 0.5f * ax, y2 = y * y;
        float num = y * (27.f + y2);
        float den = fmaf(9.f, y2, 27.f);
        float rc = fmaf(den, -5.10e-4f, 0.05081f);
        rc = rc * (2.f - den * rc);
        rc = rc * (2.f - den * rc);
        t = fminf(num * rc, 1.f);
    }
    float g = fmaf(copysignf(t, x), 0.5f, 0.5f);
    return g * e;
}

// ---------------- K1a: query projection partial GEMM ----------------
__global__ void __launch_bounds__(256) k_proj_partial(const float* __restrict__ z,
                                                      const float* __restrict__ wq) {
    __shared__ float zt[64][33];
    __shared__ float wt[64][33];
    int tid = threadIdx.x;
    int tx = tid & 15, ty = tid >> 4;
    int a_base = blockIdx.x * 128;
    int sk_base = blockIdx.y * 64;
    float acc[4][4] = {};
    for (int t = 0; t < 4; t++) {
        int a0 = a_base + t * 32;
        for (int idx = tid; idx < 64 * 32; idx += 256) {
            int r = idx >> 5, c = idx & 31;
            zt[r][c] = z[r * DA_ + a0 + c];
            wt[r][c] = wq[(size_t)(sk_base + r) * DA_ + a0 + c];
        }
        __syncthreads();
#pragma unroll
        for (int a = 0; a < 32; a++) {
            float zv[4], wv[4];
#pragma unroll
            for (int i = 0; i < 4; i++) zv[i] = zt[4 * ty + i][a];
#pragma unroll
            for (int j = 0; j < 4; j++) wv[j] = wt[4 * tx + j][a];
#pragma unroll
            for (int i = 0; i < 4; i++)
#pragma unroll
                for (int j = 0; j < 4; j++) acc[i][j] += zv[i] * wv[j];
        }
        __syncthreads();
    }
#pragma unroll
    for (int i = 0; i < 4; i++)
#pragma unroll
        for (int j = 0; j < 4; j++)
            g_qpart[blockIdx.x * (B_ * KTOT) + (4 * ty + i) * KTOT + sk_base + 4 * tx + j] = acc[i][j];
}

// ---------------- K1b: reduce + normalize + softmax + emit fragments -------
// grid 64 (b), 256 threads. warp w = aspect s; lane holds k=lane, k=lane+32.
__global__ void __launch_bounds__(256) k_qfinish(const float* __restrict__ aw) {
    __shared__ __nv_bfloat16 shq[8][64];
    int b = blockIdx.x;
    int tid = threadIdx.x;
    int s = tid >> 5, lane = tid & 31;
    int idx0 = b * KTOT + s * 64 + lane;
    int idx1 = idx0 + 32;

    float q0 = 0.f, q1 = 0.f;
#pragma unroll
    for (int p = 0; p < 16; p++) {
        q0 += g_qpart[p * (B_ * KTOT) + idx0];
        q1 += g_qpart[p * (B_ * KTOT) + idx1];
    }
    float ss = q0 * q0 + q1 * q1;
#pragma unroll
    for (int off = 16; off > 0; off >>= 1) ss += __shfl_xor_sync(0xFFFFFFFFu, ss, off);
    float m = aw[0];
#pragma unroll
    for (int i = 1; i < 8; i++) m = fmaxf(m, aw[i]);
    float den = 0.f, es = 0.f;
#pragma unroll
    for (int i = 0; i < 8; i++) {
        float e = expf(aw[i] - m);
        den += e;
        if (i == s) es = e;
    }
    float scale = (es / den) / (sqrtf(ss) + EPSF);
    float h0 = q0 * scale, h1 = q1 * scale;
    g_qhat[idx0] = h0;
    g_qhat[idx1] = h1;
    shq[s][lane] = __float2bfloat16(h0);
    shq[s][lane + 32] = __float2bfloat16(h1);
    __syncwarp();

    // emit one uint32 fragment component per lane
    int kc = lane >> 3, t = (lane >> 1) & 3, h = lane & 1;
    int col = kc * 16 + h * 8 + 2 * t;
    __nv_bfloat162 pr = __halves2bfloat162(*(__nv_bfloat16*)&shq[s][col],
                                           *(__nv_bfloat16*)&shq[s][col + 1]);
    uint32_t val = *reinterpret_cast<uint32_t*>(&pr);
    int gp = b & 15;
    int frag = (s * 4 + kc) * 4 + (b >> 4);
    int comp = 2 * h + (gp >= 8 ? 1 : 0);
    int lanep = (gp & 7) * 4 + t;
    reinterpret_cast<uint32_t*>(g_qfrag)[frag * 128 + lanep * 4 + comp] = val;
}

// ---------------- K2: bf16 HMMA score GEMM, cp.async depth-2 pipeline ------
__global__ void __launch_bounds__(256, 2) k_mma(const float* __restrict__ keys,
                                                const float* __restrict__ tau_p,
                                                const float* __restrict__ lam_p) {
    extern __shared__ char smem[];
    __shared__ float s_rs[2][64];
    __shared__ float s_bm[2][64];
    uint32_t sb = smem_u32(smem);
    int tid = threadIdx.x;
    int wid = tid >> 5, lane = tid & 31;
    int wb = wid & 3, wn = wid >> 2;
    int n0 = blockIdx.x * 128;

    int r = tid >> 1, hf = tid & 1;            // key staging: 2 threads / n-row
    int nrow = n0 + r;
    if (nrow >= N_) nrow = N_ - 1;
    const float* krow0 = keys + (size_t)nrow * DK_ + hf * 32;
    uint32_t mystg = sb + SM_STG + r * STG_STRIDE + hf * 144;

    // prologue: stage aspects 0 and 1
#pragma unroll
    for (int c = 0; c < 8; c++) cp_async16(mystg + c * 16, krow0 + c * 4);
    CP_COMMIT();
#pragma unroll
    for (int c = 0; c < 8; c++)
        cp_async16(mystg + STG_BUF + c * 16, krow0 + (size_t)N_ * DK_ + c * 4);
    CP_COMMIT();

    float acc[8][4] = {};
    int b_rowlane = wn * 64 + (lane & 7);
    int b_kof = (lane >> 3) * 8;

    for (int s = 0; s < S_; s++) {
        uint32_t stg = (s & 1) * STG_BUF;
        CP_WAIT1();
        __syncthreads();

        // LDS fp32 keys from stage, compute norm, convert+STS bf16
        float4 v[8];
        const float4* sp = reinterpret_cast<const float4*>(smem + stg + r * STG_STRIDE + hf * 144);
#pragma unroll
        for (int j = 0; j < 8; j++) v[j] = sp[j];
        float ssv = 0.f;
#pragma unroll
        for (int j = 0; j < 8; j++)
            ssv += v[j].x * v[j].x + v[j].y * v[j].y + v[j].z * v[j].z + v[j].w * v[j].w;
        ssv += __shfl_xor_sync(0xFFFFFFFFu, ssv, 1);
        float inv = rsqrtf(ssv);

        char* rowp = smem + SM_KS + (s & 1) * KSBUF + r * KSROW + hf * 64;
#pragma unroll
        for (int j = 0; j < 4; j++) {
            float4 a = v[2 * j], b4 = v[2 * j + 1];
            __nv_bfloat162 p0 = __float22bfloat162_rn(make_float2(a.x * inv, a.y * inv));
            __nv_bfloat162 p1 = __float22bfloat162_rn(make_float2(a.z * inv, a.w * inv));
            __nv_bfloat162 p2 = __float22bfloat162_rn(make_float2(b4.x * inv, b4.y * inv));
            __nv_bfloat162 p3 = __float22bfloat162_rn(make_float2(b4.z * inv, b4.w * inv));
            uint4 pk;
            pk.x = *reinterpret_cast<uint32_t*>(&p0);
            pk.y = *reinterpret_cast<uint32_t*>(&p1);
            pk.z = *reinterpret_cast<uint32_t*>(&p2);
            pk.w = *reinterpret_cast<uint32_t*>(&p3);
            *reinterpret_cast<uint4*>(rowp + j * 16) = pk;
        }
        __syncthreads();   // bf16 ready; stage buffer fully consumed

        // stage aspect s+2 into the buffer just freed
        if (s + 2 < S_) {
            const float* src = krow0 + (size_t)(s + 2) * N_ * DK_;
#pragma unroll
            for (int c = 0; c < 8; c++) cp_async16(mystg + stg + c * 16, src + c * 4);
        }
        CP_COMMIT();

        // A fragments via LDG (L2-hot, fragment-ordered)
        uint32_t afr[4][4];
#pragma unroll
        for (int kc = 0; kc < 4; kc++) {
            uint4 qf = __ldg(&g_qfrag[((s * 4 + kc) * 4 + wb) * 32 + lane]);
            afr[kc][0] = qf.x; afr[kc][1] = qf.y; afr[kc][2] = qf.z; afr[kc][3] = qf.w;
        }
        // B via ldmatrix + mma
        uint32_t bufo = SM_KS + (s & 1) * KSBUF;
#pragma unroll
        for (int ng = 0; ng < 8; ng++) {
            uint32_t baddr = sb + bufo + (b_rowlane + ng * 8) * KSROW + b_kof * 2;
            uint32_t bb[8];
            ldsm_x4(bb[0], bb[1], bb[2], bb[3], baddr);
            ldsm_x4(bb[4], bb[5], bb[6], bb[7], baddr + 64);
#pragma unroll
            for (int kc = 0; kc < 4; kc++)
                mma16816(acc[ng], afr[kc], bb[kc * 2], bb[kc * 2 + 1]);
        }
    }

    // ---- epilogue: store scores + fused rsum partial & tile max ----
    float lambda = __ldg(lam_p), tau = __ldg(tau_p);
    int brow = wb * 16 + (lane >> 2);
    int ncol0 = n0 + wn * 64 + 2 * (lane & 3);
    float rs0 = 0.f, rs1 = 0.f, bm0 = -1e30f, bm1 = -1e30f;
#pragma unroll
    for (int ng = 0; ng < 8; ng++) {
        int n = ncol0 + ng * 8;
        if (n < N_) {
            *reinterpret_cast<float2*>(&g_s[(size_t)brow * N_ + n]) =
                make_float2(acc[ng][0], acc[ng][1]);
            *reinterpret_cast<float2*>(&g_s[(size_t)(brow + 8) * N_ + n]) =
                make_float2(acc[ng][2], acc[ng][3]);
            rs0 += rsum_term(acc[ng][0], lambda, tau) + rsum_term(acc[ng][1], lambda, tau);
            rs1 += rsum_term(acc[ng][2], lambda, tau) + rsum_term(acc[ng][3], lambda, tau);
            bm0 = fmaxf(bm0, fmaxf(acc[ng][0], acc[ng][1]));
            bm1 = fmaxf(bm1, fmaxf(acc[ng][2], acc[ng][3]));
        }
    }
#pragma unroll
    for (int off = 1; off <= 2; off <<= 1) {
        rs0 += __shfl_xor_sync(0xFFFFFFFFu, rs0, off);
        rs1 += __shfl_xor_sync(0xFFFFFFFFu, rs1, off);
        bm0 = fmaxf(bm0, __shfl_xor_sync(0xFFFFFFFFu, bm0, off));
        bm1 = fmaxf(bm1, __shfl_xor_sync(0xFFFFFFFFu, bm1, off));
    }
    if ((lane & 3) == 0) {
        s_rs[wn][brow] = rs0; s_rs[wn][brow + 8] = rs1;
        s_bm[wn][brow] = bm0; s_bm[wn][brow + 8] = bm1;
    }
    __syncthreads();
    if (tid < 64) {
        g_rsp[tid * NT + blockIdx.x] = s_rs[0][tid] + s_rs[1][tid];
        g_bmax[tid * NT + blockIdx.x] = fmaxf(s_bm[0][tid], s_bm[1][tid]);
    }
}

// ---------------- K3a: per-b threshold (32nd tile-max - delta) + rsum ------
__global__ void __launch_bounds__(32) k_thresh() {
    int b = blockIdx.x;
    int lane = threadIdx.x;

    float rsum = 0.f;
    for (int i = lane; i < NT; i += 32) rsum += g_rsp[b * NT + i];
#pragma unroll
    for (int off = 16; off > 0; off >>= 1) rsum += __shfl_xor_sync(0xFFFFFFFFu, rsum, off);

    unsigned list = 0u;
    for (int i0 = 0; i0 < NT; i0 += 32) {
        int i = i0 + lane;
        unsigned key = (i < NT) ? flipf(g_bmax[b * NT + i]) : 0u;
        unsigned cm = __shfl_sync(0xFFFFFFFFu, list, 0);
        unsigned m = __ballot_sync(0xFFFFFFFFu, key > cm);
        while (m) {
            int src = __ffs(m) - 1;
            unsigned kk = __shfl_sync(0xFFFFFFFFu, key, src);
            cm = __shfl_sync(0xFFFFFFFFu, list, 0);
            if (kk > cm) {
                unsigned lt = __ballot_sync(0xFFFFFFFFu, list < kk);
                int pos = __popc(lt);
                unsigned dn = __shfl_down_sync(0xFFFFFFFFu, list, 1);
                if (lane < pos - 1) list = dn;
                else if (lane == pos - 1) list = kk;
            }
            m &= m - 1;
        }
    }
    if (lane == 0) {
        g_T[b] = unflipf(list) - DELTA;   // lane 0 holds the 32nd largest
        g_rsum[b] = rsum;
        g_ccnt[b] = 0;
    }
}

// ---------------- K3b: collect candidates >= T[b], tile-max early-out ------
__global__ void __launch_bounds__(256) k_collect() {
    __shared__ int qual[8];
    int b = blockIdx.y;
    int tid = threadIdx.x;
    float T = g_T[b];
    int tile0 = blockIdx.x * 8;
    if (tid < 8) {
        int t = tile0 + tid;
        qual[tid] = (t < NT) ? (g_bmax[b * NT + t] >= T) : 0;
    }
    __syncthreads();
    const float* srow = g_s + (size_t)b * N_;
    int base = blockIdx.x * 1024;
#pragma unroll
    for (int i = 0; i < 4; i++) {
        int n = base + i * 256 + tid;
        int tl = (i * 256 + tid) >> 7;
        if (n < N_ && qual[tl]) {
            float sv = srow[n];
            if (sv >= T) {
                int idx = atomicAdd(&g_ccnt[b], 1);
                if (idx < CAP)
                    g_cbuf[b * CAP + idx] =
                        ((unsigned long long)flipf(sv) << 32) |
                        (unsigned long long)(0xFFFFFFFFu - (unsigned)n);
            }
        }
    }
}

// ---------------- K3c: exact rescore + final top-32 + alpha ----------------
__global__ void __launch_bounds__(256) k_sel(const float* __restrict__ keys,
                                             const float* __restrict__ tau_p,
                                             const float* __restrict__ lam_p,
                                             const int* __restrict__ warm_p,
                                             int has_warm,
                                             float* __restrict__ out,
                                             int out_size) {
    __shared__ unsigned long long ex[CAP];
    __shared__ unsigned long long w32[8][32];
    int b = blockIdx.x;
    int tid = threadIdx.x;
    int wid = tid >> 5, lane = tid & 31;
    int cnt = min(g_ccnt[b], CAP);

    for (int ci = tid; ci < cnt; ci += 256) {
        unsigned long long key = g_cbuf[b * CAP + ci];
        unsigned n = 0xFFFFFFFFu - (unsigned)(key & 0xFFFFFFFFu);
        float stot = 0.f;
#pragma unroll
        for (int s = 0; s < S_; s++) {
            const float4* kp = reinterpret_cast<const float4*>(keys + ((size_t)s * N_ + n) * DK_);
            const float4* qp = reinterpret_cast<const float4*>(g_qhat + b * KTOT + s * 64);
            float ss = 0.f, dt = 0.f;
#pragma unroll
            for (int j = 0; j < 16; j++) {
                float4 kv = __ldg(kp + j);
                float4 qv = qp[j];
                ss += kv.x * kv.x + kv.y * kv.y + kv.z * kv.z + kv.w * kv.w;
                dt += kv.x * qv.x + kv.y * qv.y + kv.z * qv.z + kv.w * qv.w;
            }
            stot += dt / (sqrtf(ss) + EPSF);
        }
        ex[ci] = ((unsigned long long)flipf(stot) << 32) |
                 (unsigned long long)(0xFFFFFFFFu - n);
    }
    __syncthreads();

    unsigned long long list = 0ull;
    for (int base = wid * 32; base < cnt; base += 256) {
        int ci = base + lane;
        unsigned long long key = (ci < cnt) ? ex[ci] : 0ull;
        unsigned long long cm = __shfl_sync(0xFFFFFFFFu, list, 0);
        unsigned m = __ballot_sync(0xFFFFFFFFu, key > cm);
        while (m) {
            int src = __ffs(m) - 1;
            unsigned long long kk = __shfl_sync(0xFFFFFFFFu, key, src);
            cm = __shfl_sync(0xFFFFFFFFu, list, 0);
            if (kk > cm) {
                unsigned lt = __ballot_sync(0xFFFFFFFFu, list < kk);
                int pos = __popc(lt);
                unsigned long long dn = __shfl_down_sync(0xFFFFFFFFu, list, 1);
                if (lane < pos - 1) list = dn;
                else if (lane == pos - 1) list = kk;
            }
            m &= m - 1;
        }
    }
    w32[wid][lane] = list;
    __syncthreads();

    if (wid == 0) {
        float lambda = __ldg(lam_p), tau = __ldg(tau_p);
        unsigned long long cc[8];
#pragma unroll
        for (int i = 0; i < 8; i++) cc[i] = w32[i][lane];

        float myS = 0.f;
        int myN = 0;
        for (int round = 0; round < 32; round++) {
            unsigned long long lm = cc[0];
#pragma unroll
            for (int i = 1; i < 8; i++) lm = (cc[i] > lm) ? cc[i] : lm;
            unsigned long long mm = lm;
#pragma unroll
            for (int off = 16; off > 0; off >>= 1) {
                unsigned long long o = __shfl_xor_sync(0xFFFFFFFFu, mm, off);
                if (o > mm) mm = o;
            }
            unsigned has = __ballot_sync(0xFFFFFFFFu, lm == mm);
            int src = __ffs(has) - 1;
            if (lane == src) {
#pragma unroll
                for (int i = 0; i < 8; i++)
                    if (cc[i] == mm) cc[i] = 0ull;
            }
            if (lane == round) {
                myS = unflipf((unsigned)(mm >> 32));
                myN = (int)(0xFFFFFFFFu - (unsigned)(mm & 0xFFFFFFFFu));
            }
        }

        int warm = has_warm ? __ldg(warm_p) : 0;
        float alpha;
        if (warm) {
            float smax = __shfl_sync(0xFFFFFFFFu, myS, 0);
            float e = expf(myS - smax);
            float den = e;
#pragma unroll
            for (int off = 16; off > 0; off >>= 1) den += __shfl_xor_sync(0xFFFFFFFFu, den, off);
            alpha = e / den;
        } else {
            float rsum = g_rsum[b];
            float x = lambda * (myS - tau);
            float gg = 1.f / (1.f + expf(-x));
            float r = gg * expf(myS);
            float nr = r / (rsum + EPSF);
            float snr = nr;
#pragma unroll
            for (int off = 16; off > 0; off >>= 1) snr += __shfl_xor_sync(0xFFFFFFFFu, snr, off);
            alpha = nr / (snr + EPSF);
        }
        out[b * KMAX + lane] = alpha;
        if (out_size >= 2 * B_ * KMAX)
            out[B_ * KMAX + b * KMAX + lane] = (float)myN;
    }
}

// ---------------- host launch ----------------
extern "C" void kernel_launch(void* const* d_in, const int* in_sizes, int n_in,
                              void* d_out, int out_size) {
    const float* z    = (const float*)d_in[0];   // [64,2048]
    const float* keys = (const float*)d_in[1];   // [8,100000,64]
    const float* wq   = (const float*)d_in[2];   // [8,64,2048]
    const float* aw   = (const float*)d_in[3];   // [8]
    const float* tau  = (const float*)d_in[4];   // scalar
    const float* lam  = (const float*)d_in[5];   // scalar
    const int* warm   = (n_in > 6) ? (const int*)d_in[6] : nullptr;

    k_proj_partial<<<dim3(16, 8), 256>>>(z, wq);
    k_qfinish<<<B_, 256>>>(aw);

    cudaFuncSetAttribute(k_mma, cudaFuncAttributeMaxDynamicSharedMemorySize, SM_TOTAL);
    k_mma<<<NT, 256, SM_TOTAL>>>(keys, tau, lam);

    k_thresh<<<B_, 32>>>();
    k_collect<<<dim3(98, B_), 256>>>();
    k_sel<<<B_, 256>>>(keys, tau, lam, warm, warm != nullptr, (float*)d_out, out_size);
}

// round 7
// speedup vs baseline: 3.1737x; 1.0420x over previous
#include <cuda_runtime.h>
#include <cuda_bf16.h>
#include <math.h>
#include <stdint.h>

// Problem constants (fixed by setup_inputs)
#define B_   64
#define S_   8
#define DK_  64
#define DA_  2048
#define N_   100000
#define KTOT 512        // S_*DK_
#define KMAX 32
#define NT   782        // n-tiles of 128
#define CAP  2048       // candidate buffer per b
#define DELTA 4e-3f     // threshold safety margin (>> bf16 score noise)
#define EPSF 1e-8f

// smem layout for k_mma (bytes)
#define STG_STRIDE 288            // 256B fp32 row + split-pad (conflict-free)
#define STG_BUF (128 * STG_STRIDE)   // 36864
#define SM_STG 0                     // 2 bufs: 73728
#define KSROW 144                    // bf16 row: 128B + 16 pad
#define KSBUF (128 * KSROW)          // 18432
#define SM_KS  (2 * STG_BUF)         // 73728; 2 bufs: 36864
#define SM_TOTAL (SM_KS + 2 * KSBUF) // 110592 (108 KB) -> 2 CTAs/SM

// ---------------- device scratch ----------------
__device__ float g_qpart[16 * B_ * KTOT];
__device__ float g_qhat[B_ * KTOT];               // fp32 q̂ (exact rescore)
__device__ uint4 g_qfrag[128 * 32];               // mma A fragments (64 KB)
__device__ float g_s[(size_t)B_ * N_];            // approx scores [b][n]
__device__ float g_rsp[B_ * NT];                  // rsum partials per (b,tile)
__device__ float g_bmax[B_ * NT];                 // per-(b,tile) max
__device__ float g_T[B_];                         // collect threshold
__device__ float g_rsum[B_];                      // reduced rsum
__device__ int   g_ccnt[B_];                      // candidate counts
__device__ unsigned long long g_cbuf[B_ * CAP];   // candidates

// ================= helpers =================
__device__ __forceinline__ uint32_t smem_u32(const void* p) {
    uint32_t a;
    asm("{ .reg .u64 t; cvta.to.shared.u64 t, %1; cvt.u32.u64 %0, t; }" : "=r"(a) : "l"(p));
    return a;
}
__device__ __forceinline__ void cp_async16(uint32_t dst, const void* src) {
    asm volatile("cp.async.cg.shared.global [%0], [%1], 16;" :: "r"(dst), "l"(src));
}
#define CP_COMMIT() asm volatile("cp.async.commit_group;" ::: "memory")
#define CP_WAIT1()  asm volatile("cp.async.wait_group 1;" ::: "memory")
__device__ __forceinline__ void ldsm_x4(uint32_t& r0, uint32_t& r1, uint32_t& r2,
                                        uint32_t& r3, uint32_t addr) {
    asm volatile("ldmatrix.sync.aligned.m8n8.x4.shared.b16 {%0,%1,%2,%3}, [%4];"
                 : "=r"(r0), "=r"(r1), "=r"(r2), "=r"(r3) : "r"(addr));
}
__device__ __forceinline__ void mma16816(float* c, const uint32_t* a,
                                         uint32_t b0, uint32_t b1) {
    asm volatile(
        "mma.sync.aligned.m16n8k16.row.col.f32.bf16.bf16.f32 "
        "{%0,%1,%2,%3}, {%4,%5,%6,%7}, {%8,%9}, {%0,%1,%2,%3};"
        : "+f"(c[0]), "+f"(c[1]), "+f"(c[2]), "+f"(c[3])
        : "r"(a[0]), "r"(a[1]), "r"(a[2]), "r"(a[3]), "r"(b0), "r"(b1));
}
__device__ __forceinline__ unsigned flipf(float f) {
    unsigned u = __float_as_uint(f);
    return (u & 0x80000000u) ? ~u : (u | 0x80000000u);
}
__device__ __forceinline__ float unflipf(unsigned u) {
    return __uint_as_float((u & 0x80000000u) ? (u & 0x7FFFFFFFu) : ~u);
}
// 0-MUFU sigmoid(lambda(s-tau)) * exp(s) approximation (rsum only; ~0.1% acc)
__device__ __forceinline__ float rsum_term(float s, float lambda, float tau) {
    float e = 1.f + s * (1.f + s * (0.5f + s * (0.16666667f + s * (0.041666667f + s * 0.0083333333f))));
    float x = lambda * (s - tau);
    float ax = fabsf(x);
    float t;
    if (ax >= 4.5f) {
        t = 1.f;
    } else {
        float y = 0.5f * ax, y2 = y * y;
        float num = y * (27.f + y2);
        float den = fmaf(9.f, y2, 27.f);
        float rc = fmaf(den, -5.10e-4f, 0.05081f);
        rc = rc * (2.f - den * rc);
        rc = rc * (2.f - den * rc);
        t = fminf(num * rc, 1.f);
    }
    float g = fmaf(copysignf(t, x), 0.5f, 0.5f);
    return g * e;
}

// ---------------- K1a: query projection partial GEMM ----------------
__global__ void __launch_bounds__(256) k_proj_partial(const float* __restrict__ z,
                                                      const float* __restrict__ wq) {
    __shared__ float zt[64][33];
    __shared__ float wt[64][33];
    int tid = threadIdx.x;
    int tx = tid & 15, ty = tid >> 4;
    int a_base = blockIdx.x * 128;
    int sk_base = blockIdx.y * 64;
    float acc[4][4] = {};
    for (int t = 0; t < 4; t++) {
        int a0 = a_base + t * 32;
        for (int idx = tid; idx < 64 * 32; idx += 256) {
            int r = idx >> 5, c = idx & 31;
            zt[r][c] = z[r * DA_ + a0 + c];
            wt[r][c] = wq[(size_t)(sk_base + r) * DA_ + a0 + c];
        }
        __syncthreads();
#pragma unroll
        for (int a = 0; a < 32; a++) {
            float zv[4], wv[4];
#pragma unroll
            for (int i = 0; i < 4; i++) zv[i] = zt[4 * ty + i][a];
#pragma unroll
            for (int j = 0; j < 4; j++) wv[j] = wt[4 * tx + j][a];
#pragma unroll
            for (int i = 0; i < 4; i++)
#pragma unroll
                for (int j = 0; j < 4; j++) acc[i][j] += zv[i] * wv[j];
        }
        __syncthreads();
    }
#pragma unroll
    for (int i = 0; i < 4; i++)
#pragma unroll
        for (int j = 0; j < 4; j++)
            g_qpart[blockIdx.x * (B_ * KTOT) + (4 * ty + i) * KTOT + sk_base + 4 * tx + j] = acc[i][j];
}

// ---------------- K1b: reduce + normalize + softmax + emit fragments -------
__global__ void __launch_bounds__(256) k_qfinish(const float* __restrict__ aw) {
    __shared__ __nv_bfloat16 shq[8][64];
    int b = blockIdx.x;
    int tid = threadIdx.x;
    int s = tid >> 5, lane = tid & 31;
    int idx0 = b * KTOT + s * 64 + lane;
    int idx1 = idx0 + 32;

    float q0 = 0.f, q1 = 0.f;
#pragma unroll
    for (int p = 0; p < 16; p++) {
        q0 += g_qpart[p * (B_ * KTOT) + idx0];
        q1 += g_qpart[p * (B_ * KTOT) + idx1];
    }
    float ss = q0 * q0 + q1 * q1;
#pragma unroll
    for (int off = 16; off > 0; off >>= 1) ss += __shfl_xor_sync(0xFFFFFFFFu, ss, off);
    float m = aw[0];
#pragma unroll
    for (int i = 1; i < 8; i++) m = fmaxf(m, aw[i]);
    float den = 0.f, es = 0.f;
#pragma unroll
    for (int i = 0; i < 8; i++) {
        float e = expf(aw[i] - m);
        den += e;
        if (i == s) es = e;
    }
    float scale = (es / den) / (sqrtf(ss) + EPSF);
    float h0 = q0 * scale, h1 = q1 * scale;
    g_qhat[idx0] = h0;
    g_qhat[idx1] = h1;
    shq[s][lane] = __float2bfloat16(h0);
    shq[s][lane + 32] = __float2bfloat16(h1);
    __syncwarp();

    int kc = lane >> 3, t = (lane >> 1) & 3, h = lane & 1;
    int col = kc * 16 + h * 8 + 2 * t;
    __nv_bfloat162 pr = __halves2bfloat162(*(__nv_bfloat16*)&shq[s][col],
                                           *(__nv_bfloat16*)&shq[s][col + 1]);
    uint32_t val = *reinterpret_cast<uint32_t*>(&pr);
    int gp = b & 15;
    int frag = (s * 4 + kc) * 4 + (b >> 4);
    int comp = 2 * h + (gp >= 8 ? 1 : 0);
    int lanep = (gp & 7) * 4 + t;
    reinterpret_cast<uint32_t*>(g_qfrag)[frag * 128 + lanep * 4 + comp] = val;
}

// ---------------- K2: bf16 HMMA score GEMM, cp.async depth-2 pipeline ------
__global__ void __launch_bounds__(256, 2) k_mma(const float* __restrict__ keys,
                                                const float* __restrict__ tau_p,
                                                const float* __restrict__ lam_p) {
    extern __shared__ char smem[];
    __shared__ float s_rs[2][64];
    __shared__ float s_bm[2][64];
    uint32_t sb = smem_u32(smem);
    int tid = threadIdx.x;
    int wid = tid >> 5, lane = tid & 31;
    int wb = wid & 3, wn = wid >> 2;
    int n0 = blockIdx.x * 128;

    int r = tid >> 1, hf = tid & 1;
    int nrow = n0 + r;
    if (nrow >= N_) nrow = N_ - 1;
    const float* krow0 = keys + (size_t)nrow * DK_ + hf * 32;
    uint32_t mystg = sb + SM_STG + r * STG_STRIDE + hf * 144;

#pragma unroll
    for (int c = 0; c < 8; c++) cp_async16(mystg + c * 16, krow0 + c * 4);
    CP_COMMIT();
#pragma unroll
    for (int c = 0; c < 8; c++)
        cp_async16(mystg + STG_BUF + c * 16, krow0 + (size_t)N_ * DK_ + c * 4);
    CP_COMMIT();

    float acc[8][4] = {};
    int b_rowlane = wn * 64 + (lane & 7);
    int b_kof = (lane >> 3) * 8;

    for (int s = 0; s < S_; s++) {
        uint32_t stg = (s & 1) * STG_BUF;
        CP_WAIT1();
        __syncthreads();

        float4 v[8];
        const float4* sp = reinterpret_cast<const float4*>(smem + stg + r * STG_STRIDE + hf * 144);
#pragma unroll
        for (int j = 0; j < 8; j++) v[j] = sp[j];
        float ssv = 0.f;
#pragma unroll
        for (int j = 0; j < 8; j++)
            ssv += v[j].x * v[j].x + v[j].y * v[j].y + v[j].z * v[j].z + v[j].w * v[j].w;
        ssv += __shfl_xor_sync(0xFFFFFFFFu, ssv, 1);
        float inv = rsqrtf(ssv);

        char* rowp = smem + SM_KS + (s & 1) * KSBUF + r * KSROW + hf * 64;
#pragma unroll
        for (int j = 0; j < 4; j++) {
            float4 a = v[2 * j], b4 = v[2 * j + 1];
            __nv_bfloat162 p0 = __float22bfloat162_rn(make_float2(a.x * inv, a.y * inv));
            __nv_bfloat162 p1 = __float22bfloat162_rn(make_float2(a.z * inv, a.w * inv));
            __nv_bfloat162 p2 = __float22bfloat162_rn(make_float2(b4.x * inv, b4.y * inv));
            __nv_bfloat162 p3 = __float22bfloat162_rn(make_float2(b4.z * inv, b4.w * inv));
            uint4 pk;
            pk.x = *reinterpret_cast<uint32_t*>(&p0);
            pk.y = *reinterpret_cast<uint32_t*>(&p1);
            pk.z = *reinterpret_cast<uint32_t*>(&p2);
            pk.w = *reinterpret_cast<uint32_t*>(&p3);
            *reinterpret_cast<uint4*>(rowp + j * 16) = pk;
        }
        __syncthreads();

        if (s + 2 < S_) {
            const float* src = krow0 + (size_t)(s + 2) * N_ * DK_;
#pragma unroll
            for (int c = 0; c < 8; c++) cp_async16(mystg + stg + c * 16, src + c * 4);
        }
        CP_COMMIT();

        uint32_t afr[4][4];
#pragma unroll
        for (int kc = 0; kc < 4; kc++) {
            uint4 qf = __ldg(&g_qfrag[((s * 4 + kc) * 4 + wb) * 32 + lane]);
            afr[kc][0] = qf.x; afr[kc][1] = qf.y; afr[kc][2] = qf.z; afr[kc][3] = qf.w;
        }
        uint32_t bufo = SM_KS + (s & 1) * KSBUF;
#pragma unroll
        for (int ng = 0; ng < 8; ng++) {
            uint32_t baddr = sb + bufo + (b_rowlane + ng * 8) * KSROW + b_kof * 2;
            uint32_t bb[8];
            ldsm_x4(bb[0], bb[1], bb[2], bb[3], baddr);
            ldsm_x4(bb[4], bb[5], bb[6], bb[7], baddr + 64);
#pragma unroll
            for (int kc = 0; kc < 4; kc++)
                mma16816(acc[ng], afr[kc], bb[kc * 2], bb[kc * 2 + 1]);
        }
    }

    float lambda = __ldg(lam_p), tau = __ldg(tau_p);
    int brow = wb * 16 + (lane >> 2);
    int ncol0 = n0 + wn * 64 + 2 * (lane & 3);
    float rs0 = 0.f, rs1 = 0.f, bm0 = -1e30f, bm1 = -1e30f;
#pragma unroll
    for (int ng = 0; ng < 8; ng++) {
        int n = ncol0 + ng * 8;
        if (n < N_) {
            *reinterpret_cast<float2*>(&g_s[(size_t)brow * N_ + n]) =
                make_float2(acc[ng][0], acc[ng][1]);
            *reinterpret_cast<float2*>(&g_s[(size_t)(brow + 8) * N_ + n]) =
                make_float2(acc[ng][2], acc[ng][3]);
            rs0 += rsum_term(acc[ng][0], lambda, tau) + rsum_term(acc[ng][1], lambda, tau);
            rs1 += rsum_term(acc[ng][2], lambda, tau) + rsum_term(acc[ng][3], lambda, tau);
            bm0 = fmaxf(bm0, fmaxf(acc[ng][0], acc[ng][1]));
            bm1 = fmaxf(bm1, fmaxf(acc[ng][2], acc[ng][3]));
        }
    }
#pragma unroll
    for (int off = 1; off <= 2; off <<= 1) {
        rs0 += __shfl_xor_sync(0xFFFFFFFFu, rs0, off);
        rs1 += __shfl_xor_sync(0xFFFFFFFFu, rs1, off);
        bm0 = fmaxf(bm0, __shfl_xor_sync(0xFFFFFFFFu, bm0, off));
        bm1 = fmaxf(bm1, __shfl_xor_sync(0xFFFFFFFFu, bm1, off));
    }
    if ((lane & 3) == 0) {
        s_rs[wn][brow] = rs0; s_rs[wn][brow + 8] = rs1;
        s_bm[wn][brow] = bm0; s_bm[wn][brow + 8] = bm1;
    }
    __syncthreads();
    if (tid < 64) {
        g_rsp[tid * NT + blockIdx.x] = s_rs[0][tid] + s_rs[1][tid];
        g_bmax[tid * NT + blockIdx.x] = fmaxf(s_bm[0][tid], s_bm[1][tid]);
    }
}

// ---------------- K3a: per-b threshold (32nd tile-max - delta) + rsum ------
// 256 threads: parallel rsum reduction + 8-warp partial top-32 + merge.
__global__ void __launch_bounds__(256) k_thresh() {
    __shared__ float sh_rs[8];
    __shared__ unsigned w32[8][32];
    int b = blockIdx.x;
    int tid = threadIdx.x;
    int wid = tid >> 5, lane = tid & 31;

    float rsum = 0.f;
    for (int i = tid; i < NT; i += 256) rsum += g_rsp[b * NT + i];
#pragma unroll
    for (int off = 16; off > 0; off >>= 1) rsum += __shfl_xor_sync(0xFFFFFFFFu, rsum, off);
    if (lane == 0) sh_rs[wid] = rsum;

    // per-warp top-32 over strided slice of the 782 tile maxima
    unsigned list = 0u;
    for (int base = wid * 32; base < NT; base += 256) {
        int i = base + lane;
        unsigned key = (i < NT) ? flipf(g_bmax[b * NT + i]) : 0u;
        unsigned cm = __shfl_sync(0xFFFFFFFFu, list, 0);
        unsigned m = __ballot_sync(0xFFFFFFFFu, key > cm);
        while (m) {
            int src = __ffs(m) - 1;
            unsigned kk = __shfl_sync(0xFFFFFFFFu, key, src);
            cm = __shfl_sync(0xFFFFFFFFu, list, 0);
            if (kk > cm) {
                unsigned lt = __ballot_sync(0xFFFFFFFFu, list < kk);
                int pos = __popc(lt);
                unsigned dn = __shfl_down_sync(0xFFFFFFFFu, list, 1);
                if (lane < pos - 1) list = dn;
                else if (lane == pos - 1) list = kk;
            }
            m &= m - 1;
        }
    }
    w32[wid][lane] = list;
    __syncthreads();

    if (wid == 0) {
        unsigned cc[8];
#pragma unroll
        for (int i = 0; i < 8; i++) cc[i] = w32[i][lane];
        unsigned kept = 0u;
        for (int round = 0; round < 32; round++) {
            unsigned lm = cc[0];
#pragma unroll
            for (int i = 1; i < 8; i++) lm = (cc[i] > lm) ? cc[i] : lm;
            unsigned mm = lm;
#pragma unroll
            for (int off = 16; off > 0; off >>= 1) {
                unsigned o = __shfl_xor_sync(0xFFFFFFFFu, mm, off);
                if (o > mm) mm = o;
            }
            unsigned has = __ballot_sync(0xFFFFFFFFu, lm == mm);
            int src = __ffs(has) - 1;
            if (lane == src) {
                bool cleared = false;
#pragma unroll
                for (int i = 0; i < 8; i++) {
                    if (!cleared && cc[i] == mm) { cc[i] = 0u; cleared = true; }
                }
            }
            if (round == 31) kept = mm;   // 32nd largest (uniform across warp)
        }
        if (lane == 0) {
            float tot = 0.f;
#pragma unroll
            for (int i = 0; i < 8; i++) tot += sh_rs[i];
            g_T[b] = unflipf(kept) - DELTA;
            g_rsum[b] = tot;
            g_ccnt[b] = 0;
        }
    }
}

// ---------------- K3b: collect candidates >= T[b], tile-max early-out ------
__global__ void __launch_bounds__(256) k_collect() {
    __shared__ int qual[8];
    int b = blockIdx.y;
    int tid = threadIdx.x;
    float T = g_T[b];
    int tile0 = blockIdx.x * 8;
    if (tid < 8) {
        int t = tile0 + tid;
        qual[tid] = (t < NT) ? (g_bmax[b * NT + t] >= T) : 0;
    }
    __syncthreads();
    const float* srow = g_s + (size_t)b * N_;
    int base = blockIdx.x * 1024;
#pragma unroll
    for (int i = 0; i < 4; i++) {
        int n = base + i * 256 + tid;
        int tl = (i * 256 + tid) >> 7;
        if (n < N_ && qual[tl]) {
            float sv = srow[n];
            if (sv >= T) {
                int idx = atomicAdd(&g_ccnt[b], 1);
                if (idx < CAP)
                    g_cbuf[b * CAP + idx] =
                        ((unsigned long long)flipf(sv) << 32) |
                        (unsigned long long)(0xFFFFFFFFu - (unsigned)n);
            }
        }
    }
}

// ---------------- K3c: exact rescore + final top-32 + alpha ----------------
__global__ void __launch_bounds__(256) k_sel(const float* __restrict__ keys,
                                             const float* __restrict__ tau_p,
                                             const float* __restrict__ lam_p,
                                             const int* __restrict__ warm_p,
                                             int has_warm,
                                             float* __restrict__ out,
                                             int out_size) {
    __shared__ unsigned long long ex[CAP];
    __shared__ unsigned long long w32[8][32];
    int b = blockIdx.x;
    int tid = threadIdx.x;
    int wid = tid >> 5, lane = tid & 31;
    int cnt = min(g_ccnt[b], CAP);

    for (int ci = tid; ci < cnt; ci += 256) {
        unsigned long long key = g_cbuf[b * CAP + ci];
        unsigned n = 0xFFFFFFFFu - (unsigned)(key & 0xFFFFFFFFu);
        float stot = 0.f;
#pragma unroll
        for (int s = 0; s < S_; s++) {
            const float4* kp = reinterpret_cast<const float4*>(keys + ((size_t)s * N_ + n) * DK_);
            const float4* qp = reinterpret_cast<const float4*>(g_qhat + b * KTOT + s * 64);
            float ss = 0.f, dt = 0.f;
#pragma unroll
            for (int j = 0; j < 16; j++) {
                float4 kv = __ldg(kp + j);
                float4 qv = qp[j];
                ss += kv.x * kv.x + kv.y * kv.y + kv.z * kv.z + kv.w * kv.w;
                dt += kv.x * qv.x + kv.y * qv.y + kv.z * qv.z + kv.w * qv.w;
            }
            stot += dt / (sqrtf(ss) + EPSF);
        }
        ex[ci] = ((unsigned long long)flipf(stot) << 32) |
                 (unsigned long long)(0xFFFFFFFFu - n);
    }
    __syncthreads();

    unsigned long long list = 0ull;
    for (int base = wid * 32; base < cnt; base += 256) {
        int ci = base + lane;
        unsigned long long key = (ci < cnt) ? ex[ci] : 0ull;
        unsigned long long cm = __shfl_sync(0xFFFFFFFFu, list, 0);
        unsigned m = __ballot_sync(0xFFFFFFFFu, key > cm);
        while (m) {
            int src = __ffs(m) - 1;
            unsigned long long kk = __shfl_sync(0xFFFFFFFFu, key, src);
            cm = __shfl_sync(0xFFFFFFFFu, list, 0);
            if (kk > cm) {
                unsigned lt = __ballot_sync(0xFFFFFFFFu, list < kk);
                int pos = __popc(lt);
                unsigned long long dn = __shfl_down_sync(0xFFFFFFFFu, list, 1);
                if (lane < pos - 1) list = dn;
                else if (lane == pos - 1) list = kk;
            }
            m &= m - 1;
        }
    }
    w32[wid][lane] = list;
    __syncthreads();

    if (wid == 0) {
        float lambda = __ldg(lam_p), tau = __ldg(tau_p);
        unsigned long long cc[8];
#pragma unroll
        for (int i = 0; i < 8; i++) cc[i] = w32[i][lane];

        float myS = 0.f;
        int myN = 0;
        for (int round = 0; round < 32; round++) {
            unsigned long long lm = cc[0];
#pragma unroll
            for (int i = 1; i < 8; i++) lm = (cc[i] > lm) ? cc[i] : lm;
            unsigned long long mm = lm;
#pragma unroll
            for (int off = 16; off > 0; off >>= 1) {
                unsigned long long o = __shfl_xor_sync(0xFFFFFFFFu, mm, off);
                if (o > mm) mm = o;
            }
            unsigned has = __ballot_sync(0xFFFFFFFFu, lm == mm);
            int src = __ffs(has) - 1;
            if (lane == src) {
#pragma unroll
                for (int i = 0; i < 8; i++)
                    if (cc[i] == mm) cc[i] = 0ull;
            }
            if (lane == round) {
                myS = unflipf((unsigned)(mm >> 32));
                myN = (int)(0xFFFFFFFFu - (unsigned)(mm & 0xFFFFFFFFu));
            }
        }

        int warm = has_warm ? __ldg(warm_p) : 0;
        float alpha;
        if (warm) {
            float smax = __shfl_sync(0xFFFFFFFFu, myS, 0);
            float e = expf(myS - smax);
            float den = e;
#pragma unroll
            for (int off = 16; off > 0; off >>= 1) den += __shfl_xor_sync(0xFFFFFFFFu, den, off);
            alpha = e / den;
        } else {
            float rsum = g_rsum[b];
            float x = lambda * (myS - tau);
            float gg = 1.f / (1.f + expf(-x));
            float r = gg * expf(myS);
            float nr = r / (rsum + EPSF);
            float snr = nr;
#pragma unroll
            for (int off = 16; off > 0; off >>= 1) snr += __shfl_xor_sync(0xFFFFFFFFu, snr, off);
            alpha = nr / (snr + EPSF);
        }
        out[b * KMAX + lane] = alpha;
        if (out_size >= 2 * B_ * KMAX)
            out[B_ * KMAX + b * KMAX + lane] = (float)myN;
    }
}

// ---------------- host launch ----------------
extern "C" void kernel_launch(void* const* d_in, const int* in_sizes, int n_in,
                              void* d_out, int out_size) {
    const float* z    = (const float*)d_in[0];   // [64,2048]
    const float* keys = (const float*)d_in[1];   // [8,100000,64]
    const float* wq   = (const float*)d_in[2];   // [8,64,2048]
    const float* aw   = (const float*)d_in[3];   // [8]
    const float* tau  = (const float*)d_in[4];   // scalar
    const float* lam  = (const float*)d_in[5];   // scalar
    const int* warm   = (n_in > 6) ? (const int*)d_in[6] : nullptr;

    k_proj_partial<<<dim3(16, 8), 256>>>(z, wq);
    k_qfinish<<<B_, 256>>>(aw);

    cudaFuncSetAttribute(k_mma, cudaFuncAttributeMaxDynamicSharedMemorySize, SM_TOTAL);
    k_mma<<<NT, 256, SM_TOTAL>>>(keys, tau, lam);

    k_thresh<<<B_, 256>>>();
    k_collect<<<dim3(98, B_), 256>>>();
    k_sel<<<B_, 256>>>(keys, tau, lam, warm, warm != nullptr, (float*)d_out, out_size);
}